// round 6
// baseline (speedup 1.0000x reference)
#include <cuda_runtime.h>
#include <cuda_bf16.h>
#include <cstdint>

// Shapes (fixed by the problem)
#define B_   16
#define T_   12
#define N_   1000
#define F_   64
#define KC_  3
#define OUT_ 64

#define KJ_   3000            // contraction dim kj = k*1000 + j
#define KJP_  3008            // padded (mult of 32)
#define MP_   1024            // i padded
#define TO_   768             // t*64 + o

// Scratch (zero-initialized at module load; pad regions never written -> stay 0)
__device__ __align__(256) float g_ThT[KC_ * OUT_ * F_];                  // tf32
__device__ __align__(256) __nv_bfloat16 g_yh[(size_t)B_ * TO_ * KJP_];   // y hi
__device__ __align__(256) __nv_bfloat16 g_yl[(size_t)B_ * TO_ * KJP_];   // y lo
__device__ __align__(256) __nv_bfloat16 g_Ah[(size_t)B_ * MP_ * KJP_];   // A hi
__device__ __align__(256) __nv_bfloat16 g_Al[(size_t)B_ * MP_ * KJP_];   // A lo

__device__ __forceinline__ float to_tf32(float v) {
    uint32_t u;
    asm("cvt.rna.tf32.f32 %0, %1;" : "=r"(u) : "f"(v));
    return __uint_as_float(u);
}

__device__ __forceinline__ void split_bf(float v, __nv_bfloat16& h, __nv_bfloat16& l) {
    h = __float2bfloat16_rn(v);
    l = __float2bfloat16_rn(v - __bfloat162float(h));
}

__device__ __forceinline__ void cpasync16(uint32_t dst, const void* src) {
    asm volatile("cp.async.cg.shared.global [%0], [%1], 16;" :: "r"(dst), "l"(src));
}

__device__ __forceinline__ uint32_t smem_u32(const void* p) {
    uint32_t a;
    asm("{ .reg .u64 t; cvta.to.shared.u64 t, %1; cvt.u32.u64 %0, t; }"
        : "=r"(a) : "l"(p));
    return a;
}

// ---------------------------------------------------------------------------
// Kernel 0: ThT[(k*64+o)][f] = tf32(Theta[k,f,o])
// ---------------------------------------------------------------------------
__global__ __launch_bounds__(256) void k_thetaT(const float* __restrict__ Theta)
{
    for (int idx = threadIdx.x; idx < KC_ * OUT_ * F_; idx += 256) {
        const int f  = idx & 63;
        const int ko = idx >> 6;
        const int k  = ko >> 6;
        const int o  = ko & 63;
        g_ThT[idx] = to_tf32(Theta[(k * F_ + f) * OUT_ + o]);
    }
}

// ---------------------------------------------------------------------------
// Kernel 1: feature transform (mma.sync tf32); epilogue writes bf16 hi/lo
//   y[b][t*64+o][k*1000+j] = sum_f ThT[(k*64+o)][f] * x[b,t,j,f]
// ---------------------------------------------------------------------------
__global__ __launch_bounds__(256) void k_featT_tc(const float* __restrict__ x)
{
    __shared__ float As[64][36];
    __shared__ float Bs[128][36];

    const int j0 = blockIdx.x * 128;
    const int m0 = blockIdx.y * 64;
    const int bt = blockIdx.z;
    const int b  = bt / T_;
    const int t  = bt % T_;

    const int tid  = threadIdx.x;
    const int lane = tid & 31;
    const int w    = tid >> 5;
    const int wm   = (w & 1) * 32;
    const int wn   = (w >> 1) * 32;

    const float* __restrict__ xp = x + (size_t)bt * N_ * F_;

    float c[2][4][4];
    #pragma unroll
    for (int mt = 0; mt < 2; mt++)
        #pragma unroll
        for (int nt = 0; nt < 4; nt++)
            #pragma unroll
            for (int q = 0; q < 4; q++) c[mt][nt][q] = 0.f;

    const uint32_t as_base = smem_u32(&As[0][0]);
    const uint32_t bs_base = smem_u32(&Bs[0][0]);

    const int a_row  = lane & 15;
    const int a_col4 = (lane >> 4) * 4;
    const int b_row  = (lane & 7) + ((lane & 16) >> 1);
    const int b_col4 = ((lane >> 3) & 1) * 4;

    #pragma unroll
    for (int kt = 0; kt < 2; kt++) {
        const int f0 = kt * 32;
        #pragma unroll
        for (int l = 0; l < 2; l++) {
            int idx = tid + l * 256;
            int row = idx >> 3, c4 = (idx & 7) * 4;
            *(float4*)&As[row][c4] = *(const float4*)&g_ThT[(m0 + row) * F_ + f0 + c4];
        }
        #pragma unroll
        for (int l = 0; l < 4; l++) {
            int idx = tid + l * 256;
            int row = idx >> 3, c4 = (idx & 7) * 4;
            float4 v;
            if (j0 + row < N_) {
                v = *(const float4*)&xp[(size_t)(j0 + row) * F_ + f0 + c4];
                v.x = to_tf32(v.x); v.y = to_tf32(v.y);
                v.z = to_tf32(v.z); v.w = to_tf32(v.w);
            } else {
                v = make_float4(0.f, 0.f, 0.f, 0.f);
            }
            *(float4*)&Bs[row][c4] = v;
        }
        __syncthreads();

        #pragma unroll
        for (int ks = 0; ks < 4; ks++) {
            const int k0 = ks * 8;
            uint32_t a[2][4];
            #pragma unroll
            for (int mt = 0; mt < 2; mt++) {
                uint32_t addr = as_base +
                    (uint32_t)(((wm + mt * 16 + a_row) * 36 + k0 + a_col4) * 4);
                asm volatile(
                    "ldmatrix.sync.aligned.m8n8.x4.shared.b16 {%0,%1,%2,%3}, [%4];"
                    : "=r"(a[mt][0]), "=r"(a[mt][1]), "=r"(a[mt][2]), "=r"(a[mt][3])
                    : "r"(addr));
            }
            uint32_t bb[4][2];
            #pragma unroll
            for (int nb = 0; nb < 2; nb++) {
                uint32_t addr = bs_base +
                    (uint32_t)(((wn + nb * 16 + b_row) * 36 + k0 + b_col4) * 4);
                uint32_t r0, r1, r2, r3;
                asm volatile(
                    "ldmatrix.sync.aligned.m8n8.x4.shared.b16 {%0,%1,%2,%3}, [%4];"
                    : "=r"(r0), "=r"(r1), "=r"(r2), "=r"(r3)
                    : "r"(addr));
                bb[nb * 2][0] = r0;     bb[nb * 2][1] = r1;
                bb[nb * 2 + 1][0] = r2; bb[nb * 2 + 1][1] = r3;
            }
            #pragma unroll
            for (int mt = 0; mt < 2; mt++)
                #pragma unroll
                for (int nt = 0; nt < 4; nt++)
                    asm volatile(
                        "mma.sync.aligned.m16n8k8.row.col.f32.tf32.tf32.f32 "
                        "{%0,%1,%2,%3}, {%4,%5,%6,%7}, {%8,%9}, {%0,%1,%2,%3};"
                        : "+f"(c[mt][nt][0]), "+f"(c[mt][nt][1]),
                          "+f"(c[mt][nt][2]), "+f"(c[mt][nt][3])
                        : "r"(a[mt][0]), "r"(a[mt][1]), "r"(a[mt][2]), "r"(a[mt][3]),
                          "r"(bb[nt][0]), "r"(bb[nt][1]));
        }
        __syncthreads();
    }

    // Epilogue: split fp32 accum into bf16 hi/lo planes (kj-contiguous)
    const int gid = lane >> 2;
    const int tig = lane & 3;
    #pragma unroll
    for (int mt = 0; mt < 2; mt++) {
        #pragma unroll
        for (int half = 0; half < 2; half++) {
            const int ko = m0 + wm + mt * 16 + half * 8 + gid;
            const int k  = ko >> 6;
            const int o  = ko & 63;
            const size_t rowbase = ((size_t)b * TO_ + t * OUT_ + o) * KJP_ + (size_t)k * N_;
            #pragma unroll
            for (int nt = 0; nt < 4; nt++) {
                const int j = j0 + wn + nt * 8 + tig * 2;
                if (j < N_) {
                    __nv_bfloat16 h0, l0, h1, l1;
                    split_bf(c[mt][nt][half * 2 + 0], h0, l0);
                    split_bf(c[mt][nt][half * 2 + 1], h1, l1);
                    __nv_bfloat162 hv; hv.x = h0; hv.y = h1;
                    __nv_bfloat162 lv; lv.x = l0; lv.y = l1;
                    *(__nv_bfloat162*)&g_yh[rowbase + j] = hv;
                    *(__nv_bfloat162*)&g_yl[rowbase + j] = lv;
                }
            }
        }
    }
}

// ---------------------------------------------------------------------------
// Kernel 2: A[b][i][kj] = cheb[kj,i] * SAtt[b, kj%1000, i]  -> bf16 hi/lo
// ---------------------------------------------------------------------------
__global__ __launch_bounds__(256) void k_buildA(
    const float* __restrict__ SAtt,
    const float* __restrict__ cheb)
{
    __shared__ float buf[256][33];
    const int b    = blockIdx.z;
    const int i0   = blockIdx.y * 32;
    const int kjc  = blockIdx.x * 256;
    const int lane = threadIdx.x & 31;
    const int w    = threadIdx.x >> 5;
    const int i    = i0 + lane;

    const float* __restrict__ sb = SAtt + (size_t)b * N_ * N_;

    #pragma unroll 4
    for (int r = 0; r < 32; r++) {
        int kj = kjc + w * 32 + r;
        float v = 0.f;
        if (kj < KJ_ && i < N_) {
            int k = (kj >= 2000) ? 2 : (kj >= 1000 ? 1 : 0);
            int j = kj - k * 1000;
            v = __ldg(cheb + (size_t)kj * N_ + i) * __ldg(sb + (size_t)j * N_ + i);
        }
        buf[w * 32 + r][lane] = v;
    }
    __syncthreads();

    #pragma unroll
    for (int rr = 0; rr < 4; rr++) {
        int iw = i0 + w * 4 + rr;
        if (iw < N_) {
            const size_t rowbase = ((size_t)b * MP_ + iw) * KJP_;
            #pragma unroll
            for (int c = 0; c < 8; c++) {
                int kj = kjc + c * 32 + lane;
                if (kj < KJ_) {
                    __nv_bfloat16 h, l;
                    split_bf(buf[c * 32 + lane][w * 4 + rr], h, l);
                    g_Ah[rowbase + kj] = h;
                    g_Al[rowbase + kj] = l;
                }
            }
        }
    }
}

// ---------------------------------------------------------------------------
// Kernel 3: spatial GEMM, split-bf16 (3 products), m16n8k16 mma.sync,
// BK=32, cp.async double-buffered, one sync per tile.
//   D = relu( Ah*yh + Ah*yl + Al*yh )   (accumulated fp32)
// ---------------------------------------------------------------------------
#define SBK    32
#define NTILE  (KJP_ / SBK)          // 94
#define ROWE   40                    // bf16 elems per smem row (80B, pad)
#define PART_E (128 * ROWE)          // bf16 elems per operand-part per stage

__global__ __launch_bounds__(256, 2) void k_spatial_bf(float* __restrict__ out)
{
    extern __shared__ __nv_bfloat16 sm[];
    // layout: [stage][part 0..3 = Ah, Al, Bh, Bl][128][40]

    const int b  = blockIdx.z;
    const int i0 = blockIdx.y * 128;
    const int n0 = blockIdx.x * 128;

    const int tid  = threadIdx.x;
    const int lane = tid & 31;
    const int w    = tid >> 5;
    const int im   = (w & 3) * 32;
    const int in_  = (w >> 2) * 64;

    const __nv_bfloat16* __restrict__ pAh = g_Ah + ((size_t)b * MP_ + i0) * KJP_;
    const __nv_bfloat16* __restrict__ pAl = g_Al + ((size_t)b * MP_ + i0) * KJP_;
    const __nv_bfloat16* __restrict__ pBh = g_yh + ((size_t)b * TO_ + n0) * KJP_;
    const __nv_bfloat16* __restrict__ pBl = g_yl + ((size_t)b * TO_ + n0) * KJP_;

    float c[2][8][4];
    #pragma unroll
    for (int mt = 0; mt < 2; mt++)
        #pragma unroll
        for (int nt = 0; nt < 8; nt++)
            #pragma unroll
            for (int q = 0; q < 4; q++) c[mt][nt][q] = 0.f;

    const uint32_t s_base = smem_u32(sm);
    // part bases per stage s: s_base + ((s*4 + part) * PART_E) * 2 bytes

    // loader geometry: per part, 512 16B-chunks; 2 per thread
    const int ld_row = tid >> 1;            // 0..127
    const int ld_ch0 = (tid & 1) * 2;       // chunk 0 or 2 (each chunk = 8 bf16)

    // fragment geometry
    const int a_row = lane & 15;
    const int a_k8  = lane >> 4;            // 0/1 -> k8 half
    const int b_row = (lane & 7) + ((lane & 16) >> 1);
    const int b_k8  = (lane >> 3) & 1;

    #define LOAD_TILE(p, s) do {                                                \
        const uint32_t sb_ = s_base + (uint32_t)((s) * 4 * PART_E * 2);         \
        const size_t go = (size_t)ld_row * KJP_ + (p) + ld_ch0 * 8;             \
        const uint32_t so = (uint32_t)(ld_row * ROWE + ld_ch0 * 8) * 2;         \
        cpasync16(sb_ + 0 * PART_E * 2 + so,      pAh + go);                    \
        cpasync16(sb_ + 0 * PART_E * 2 + so + 16, pAh + go + 8);                \
        cpasync16(sb_ + 1 * PART_E * 2 + so,      pAl + go);                    \
        cpasync16(sb_ + 1 * PART_E * 2 + so + 16, pAl + go + 8);                \
        cpasync16(sb_ + 2 * PART_E * 2 + so,      pBh + go);                    \
        cpasync16(sb_ + 2 * PART_E * 2 + so + 16, pBh + go + 8);                \
        cpasync16(sb_ + 3 * PART_E * 2 + so,      pBl + go);                    \
        cpasync16(sb_ + 3 * PART_E * 2 + so + 16, pBl + go + 8);                \
        asm volatile("cp.async.commit_group;");                                 \
    } while (0)

    LOAD_TILE(0, 0);

    for (int pc = 0; pc < NTILE; pc++) {
        const int cur = pc & 1;
        asm volatile("cp.async.wait_group 0;");
        __syncthreads();

        if (pc + 1 < NTILE) LOAD_TILE((pc + 1) * SBK, cur ^ 1);

        const uint32_t st = s_base + (uint32_t)(cur * 4 * PART_E * 2);
        const uint32_t sAh = st;
        const uint32_t sAl = st + PART_E * 2;
        const uint32_t sBh = st + 2 * PART_E * 2;
        const uint32_t sBl = st + 3 * PART_E * 2;

        #pragma unroll
        for (int ks = 0; ks < 2; ks++) {
            const int kb = ks * 16;      // bf16 col offset of this k16 step

            uint32_t ah[2][4], al[2][4];
            #pragma unroll
            for (int mt = 0; mt < 2; mt++) {
                const uint32_t off =
                    (uint32_t)(((im + mt * 16 + a_row) * ROWE + kb + a_k8 * 8) * 2);
                asm volatile(
                    "ldmatrix.sync.aligned.m8n8.x4.shared.b16 {%0,%1,%2,%3}, [%4];"
                    : "=r"(ah[mt][0]), "=r"(ah[mt][1]), "=r"(ah[mt][2]), "=r"(ah[mt][3])
                    : "r"(sAh + off));
                asm volatile(
                    "ldmatrix.sync.aligned.m8n8.x4.shared.b16 {%0,%1,%2,%3}, [%4];"
                    : "=r"(al[mt][0]), "=r"(al[mt][1]), "=r"(al[mt][2]), "=r"(al[mt][3])
                    : "r"(sAl + off));
            }

            uint32_t bb[8][2];
            // --- B hi: Ah*Bh + Al*Bh
            #pragma unroll
            for (int nb = 0; nb < 4; nb++) {
                const uint32_t off =
                    (uint32_t)(((in_ + nb * 16 + b_row) * ROWE + kb + b_k8 * 8) * 2);
                uint32_t r0, r1, r2, r3;
                asm volatile(
                    "ldmatrix.sync.aligned.m8n8.x4.shared.b16 {%0,%1,%2,%3}, [%4];"
                    : "=r"(r0), "=r"(r1), "=r"(r2), "=r"(r3)
                    : "r"(sBh + off));
                bb[nb * 2][0] = r0;     bb[nb * 2][1] = r1;
                bb[nb * 2 + 1][0] = r2; bb[nb * 2 + 1][1] = r3;
            }
            #pragma unroll
            for (int mt = 0; mt < 2; mt++)
                #pragma unroll
                for (int nt = 0; nt < 8; nt++) {
                    asm volatile(
                        "mma.sync.aligned.m16n8k16.row.col.f32.bf16.bf16.f32 "
                        "{%0,%1,%2,%3}, {%4,%5,%6,%7}, {%8,%9}, {%0,%1,%2,%3};"
                        : "+f"(c[mt][nt][0]), "+f"(c[mt][nt][1]),
                          "+f"(c[mt][nt][2]), "+f"(c[mt][nt][3])
                        : "r"(ah[mt][0]), "r"(ah[mt][1]), "r"(ah[mt][2]), "r"(ah[mt][3]),
                          "r"(bb[nt][0]), "r"(bb[nt][1]));
                    asm volatile(
                        "mma.sync.aligned.m16n8k16.row.col.f32.bf16.bf16.f32 "
                        "{%0,%1,%2,%3}, {%4,%5,%6,%7}, {%8,%9}, {%0,%1,%2,%3};"
                        : "+f"(c[mt][nt][0]), "+f"(c[mt][nt][1]),
                          "+f"(c[mt][nt][2]), "+f"(c[mt][nt][3])
                        : "r"(al[mt][0]), "r"(al[mt][1]), "r"(al[mt][2]), "r"(al[mt][3]),
                          "r"(bb[nt][0]), "r"(bb[nt][1]));
                }
            // --- B lo: Ah*Bl (reuse bb regs)
            #pragma unroll
            for (int nb = 0; nb < 4; nb++) {
                const uint32_t off =
                    (uint32_t)(((in_ + nb * 16 + b_row) * ROWE + kb + b_k8 * 8) * 2);
                uint32_t r0, r1, r2, r3;
                asm volatile(
                    "ldmatrix.sync.aligned.m8n8.x4.shared.b16 {%0,%1,%2,%3}, [%4];"
                    : "=r"(r0), "=r"(r1), "=r"(r2), "=r"(r3)
                    : "r"(sBl + off));
                bb[nb * 2][0] = r0;     bb[nb * 2][1] = r1;
                bb[nb * 2 + 1][0] = r2; bb[nb * 2 + 1][1] = r3;
            }
            #pragma unroll
            for (int mt = 0; mt < 2; mt++)
                #pragma unroll
                for (int nt = 0; nt < 8; nt++)
                    asm volatile(
                        "mma.sync.aligned.m16n8k16.row.col.f32.bf16.bf16.f32 "
                        "{%0,%1,%2,%3}, {%4,%5,%6,%7}, {%8,%9}, {%0,%1,%2,%3};"
                        : "+f"(c[mt][nt][0]), "+f"(c[mt][nt][1]),
                          "+f"(c[mt][nt][2]), "+f"(c[mt][nt][3])
                        : "r"(ah[mt][0]), "r"(ah[mt][1]), "r"(ah[mt][2]), "r"(ah[mt][3]),
                          "r"(bb[nt][0]), "r"(bb[nt][1]));
        }
        __syncthreads();
    }

    // Epilogue with fused relu
    const int gid = lane >> 2;
    const int tig = lane & 3;
    #pragma unroll
    for (int mt = 0; mt < 2; mt++) {
        #pragma unroll
        for (int half = 0; half < 2; half++) {
            const int i = i0 + im + mt * 16 + half * 8 + gid;
            if (i < N_) {
                #pragma unroll
                for (int nt = 0; nt < 8; nt++) {
                    const int to = n0 + in_ + nt * 8 + tig * 2;
                    const int t  = to >> 6;
                    const int o  = to & 63;
                    float2 v;
                    v.x = fmaxf(c[mt][nt][half * 2 + 0], 0.f);
                    v.y = fmaxf(c[mt][nt][half * 2 + 1], 0.f);
                    *(float2*)&out[(size_t)b * (T_ * N_ * OUT_) +
                                   (size_t)t * (N_ * OUT_) +
                                   (size_t)i * OUT_ + o] = v;
                }
            }
        }
    }
}

// ---------------------------------------------------------------------------
// Launch
// ---------------------------------------------------------------------------
extern "C" void kernel_launch(void* const* d_in, const int* in_sizes, int n_in,
                              void* d_out, int out_size)
{
    const float* x     = (const float*)d_in[0];
    const float* SAtt  = (const float*)d_in[1];
    const float* cheb  = (const float*)d_in[2];
    const float* Theta = (const float*)d_in[3];
    float* out = (float*)d_out;

    const int smem_bf = 2 * 4 * PART_E * 2;   // 2 stages x 4 parts x 10240B = 81920
    cudaFuncSetAttribute(k_spatial_bf,
                         cudaFuncAttributeMaxDynamicSharedMemorySize, smem_bf);

    k_thetaT<<<1, 256>>>(Theta);
    k_featT_tc<<<dim3(8, 3, B_ * T_), 256>>>(x);
    k_buildA<<<dim3(12, 32, B_), 256>>>(SAtt, cheb);
    k_spatial_bf<<<dim3(TO_ / 128, MP_ / 128, B_), 256, smem_bf>>>(out);
}

// round 7
// speedup vs baseline: 1.4348x; 1.4348x over previous
#include <cuda_runtime.h>
#include <cstdint>

// Shapes (fixed by the problem)
#define B_   16
#define T_   12
#define N_   1000
#define F_   64
#define KC_  3
#define OUT_ 64

#define KJ_   3000            // contraction dim kj = k*1000 + j
#define KJP_  3008            // padded (mult of 32)
#define MP_   1024            // i padded
#define TO_   768             // t*64 + o

// Scratch (zero-initialized at module load; pad regions never written -> stay 0)
__device__ __align__(256) float g_ThT[KC_ * OUT_ * F_];          // tf32
__device__ __align__(256) float g_yT[(size_t)B_ * TO_ * KJP_];   // yT[b][to][kjp]
__device__ __align__(256) float g_AT[(size_t)B_ * MP_ * KJP_];   // AT[b][i][kjp]

__device__ __forceinline__ float to_tf32(float v) {
    uint32_t u;
    asm("cvt.rna.tf32.f32 %0, %1;" : "=r"(u) : "f"(v));
    return __uint_as_float(u);
}

__device__ __forceinline__ void cpasync16(uint32_t dst, const void* src) {
    asm volatile("cp.async.cg.shared.global [%0], [%1], 16;" :: "r"(dst), "l"(src));
}

__device__ __forceinline__ uint32_t smem_u32(const void* p) {
    uint32_t a;
    asm("{ .reg .u64 t; cvta.to.shared.u64 t, %1; cvt.u32.u64 %0, t; }"
        : "=r"(a) : "l"(p));
    return a;
}

// ---------------------------------------------------------------------------
// Kernel 0: ThT[(k*64+o)][f] = tf32(Theta[k,f,o])
// ---------------------------------------------------------------------------
__global__ __launch_bounds__(256) void k_thetaT(const float* __restrict__ Theta)
{
    for (int idx = threadIdx.x; idx < KC_ * OUT_ * F_; idx += 256) {
        const int f  = idx & 63;
        const int ko = idx >> 6;
        const int k  = ko >> 6;
        const int o  = ko & 63;
        g_ThT[idx] = to_tf32(Theta[(k * F_ + f) * OUT_ + o]);
    }
}

// ---------------------------------------------------------------------------
// Kernel 1: feature transform (mma.sync tf32), transposed output (kj-contig)
//   yT[b][t*64+o][k*1000+j] = sum_f ThT[(k*64+o)][f] * x[b,t,j,f]
// ---------------------------------------------------------------------------
__global__ __launch_bounds__(256) void k_featT_tc(const float* __restrict__ x)
{
    __shared__ float As[64][36];
    __shared__ float Bs[128][36];

    const int j0 = blockIdx.x * 128;
    const int m0 = blockIdx.y * 64;
    const int bt = blockIdx.z;
    const int b  = bt / T_;
    const int t  = bt % T_;

    const int tid  = threadIdx.x;
    const int lane = tid & 31;
    const int w    = tid >> 5;
    const int wm   = (w & 1) * 32;
    const int wn   = (w >> 1) * 32;

    const float* __restrict__ xp = x + (size_t)bt * N_ * F_;

    float c[2][4][4];
    #pragma unroll
    for (int mt = 0; mt < 2; mt++)
        #pragma unroll
        for (int nt = 0; nt < 4; nt++)
            #pragma unroll
            for (int q = 0; q < 4; q++) c[mt][nt][q] = 0.f;

    const uint32_t as_base = smem_u32(&As[0][0]);
    const uint32_t bs_base = smem_u32(&Bs[0][0]);

    const int a_row  = lane & 15;
    const int a_col4 = (lane >> 4) * 4;
    const int b_row  = (lane & 7) + ((lane & 16) >> 1);
    const int b_col4 = ((lane >> 3) & 1) * 4;

    #pragma unroll
    for (int kt = 0; kt < 2; kt++) {
        const int f0 = kt * 32;
        #pragma unroll
        for (int l = 0; l < 2; l++) {
            int idx = tid + l * 256;
            int row = idx >> 3, c4 = (idx & 7) * 4;
            *(float4*)&As[row][c4] = *(const float4*)&g_ThT[(m0 + row) * F_ + f0 + c4];
        }
        #pragma unroll
        for (int l = 0; l < 4; l++) {
            int idx = tid + l * 256;
            int row = idx >> 3, c4 = (idx & 7) * 4;
            float4 v;
            if (j0 + row < N_) {
                v = *(const float4*)&xp[(size_t)(j0 + row) * F_ + f0 + c4];
                v.x = to_tf32(v.x); v.y = to_tf32(v.y);
                v.z = to_tf32(v.z); v.w = to_tf32(v.w);
            } else {
                v = make_float4(0.f, 0.f, 0.f, 0.f);
            }
            *(float4*)&Bs[row][c4] = v;
        }
        __syncthreads();

        #pragma unroll
        for (int ks = 0; ks < 4; ks++) {
            const int k0 = ks * 8;
            uint32_t a[2][4];
            #pragma unroll
            for (int mt = 0; mt < 2; mt++) {
                uint32_t addr = as_base +
                    (uint32_t)(((wm + mt * 16 + a_row) * 36 + k0 + a_col4) * 4);
                asm volatile(
                    "ldmatrix.sync.aligned.m8n8.x4.shared.b16 {%0,%1,%2,%3}, [%4];"
                    : "=r"(a[mt][0]), "=r"(a[mt][1]), "=r"(a[mt][2]), "=r"(a[mt][3])
                    : "r"(addr));
            }
            uint32_t bb[4][2];
            #pragma unroll
            for (int nb = 0; nb < 2; nb++) {
                uint32_t addr = bs_base +
                    (uint32_t)(((wn + nb * 16 + b_row) * 36 + k0 + b_col4) * 4);
                uint32_t r0, r1, r2, r3;
                asm volatile(
                    "ldmatrix.sync.aligned.m8n8.x4.shared.b16 {%0,%1,%2,%3}, [%4];"
                    : "=r"(r0), "=r"(r1), "=r"(r2), "=r"(r3)
                    : "r"(addr));
                bb[nb * 2][0] = r0;     bb[nb * 2][1] = r1;
                bb[nb * 2 + 1][0] = r2; bb[nb * 2 + 1][1] = r3;
            }
            #pragma unroll
            for (int mt = 0; mt < 2; mt++)
                #pragma unroll
                for (int nt = 0; nt < 4; nt++)
                    asm volatile(
                        "mma.sync.aligned.m16n8k8.row.col.f32.tf32.tf32.f32 "
                        "{%0,%1,%2,%3}, {%4,%5,%6,%7}, {%8,%9}, {%0,%1,%2,%3};"
                        : "+f"(c[mt][nt][0]), "+f"(c[mt][nt][1]),
                          "+f"(c[mt][nt][2]), "+f"(c[mt][nt][3])
                        : "r"(a[mt][0]), "r"(a[mt][1]), "r"(a[mt][2]), "r"(a[mt][3]),
                          "r"(bb[nt][0]), "r"(bb[nt][1]));
        }
        __syncthreads();
    }

    const int gid = lane >> 2;
    const int tig = lane & 3;
    #pragma unroll
    for (int mt = 0; mt < 2; mt++) {
        #pragma unroll
        for (int half = 0; half < 2; half++) {
            const int ko = m0 + wm + mt * 16 + half * 8 + gid;
            const int k  = ko >> 6;
            const int o  = ko & 63;
            float* __restrict__ dst =
                g_yT + ((size_t)b * TO_ + t * OUT_ + o) * KJP_ + k * N_;
            #pragma unroll
            for (int nt = 0; nt < 4; nt++) {
                const int j = j0 + wn + nt * 8 + tig * 2;
                if (j < N_) {
                    float2 v;
                    v.x = to_tf32(c[mt][nt][half * 2 + 0]);
                    v.y = to_tf32(c[mt][nt][half * 2 + 1]);
                    *(float2*)&dst[j] = v;
                }
            }
        }
    }
}

// ---------------------------------------------------------------------------
// Kernel 2: AT[b][i][kj] = tf32( cheb[kj,i] * SAtt[b, kj%1000, i] )
// cheb tile cached in registers; b loop inside block (cheb read once, not 16x)
// ---------------------------------------------------------------------------
__global__ __launch_bounds__(256) void k_buildA(
    const float* __restrict__ SAtt,
    const float* __restrict__ cheb)
{
    __shared__ float buf[256][33];
    const int i0   = blockIdx.y * 32;
    const int kjc  = blockIdx.x * 256;
    const int lane = threadIdx.x & 31;
    const int w    = threadIdx.x >> 5;
    const int i    = i0 + lane;

    // cache cheb[kj, i] for this thread's 32 kj rows
    float ch[32];
    int   jj[32];
    bool  ok[32];
    #pragma unroll 8
    for (int r = 0; r < 32; r++) {
        const int kj = kjc + w * 32 + r;
        ok[r] = (kj < KJ_) && (i < N_);
        const int k = (kj >= 2000) ? 2 : (kj >= 1000 ? 1 : 0);
        jj[r] = (kj < KJ_) ? (kj - k * 1000) : 0;
        ch[r] = ok[r] ? __ldg(cheb + (size_t)kj * N_ + i) : 0.f;
    }

    for (int b = 0; b < B_; b++) {
        const float* __restrict__ sb = SAtt + (size_t)b * N_ * N_;
        #pragma unroll 8
        for (int r = 0; r < 32; r++) {
            float v = 0.f;
            if (ok[r]) v = ch[r] * __ldg(sb + (size_t)jj[r] * N_ + i);
            buf[w * 32 + r][lane] = v;
        }
        __syncthreads();

        #pragma unroll
        for (int rr = 0; rr < 4; rr++) {
            const int iw = i0 + w * 4 + rr;
            if (iw < N_) {
                float* __restrict__ outp = g_AT + ((size_t)b * MP_ + iw) * KJP_;
                #pragma unroll
                for (int c = 0; c < 8; c++) {
                    const int kj = kjc + c * 32 + lane;
                    if (kj < KJ_)
                        outp[kj] = to_tf32(buf[c * 32 + lane][w * 4 + rr]);
                }
            }
        }
        __syncthreads();
    }
}

// ---------------------------------------------------------------------------
// Kernel 3: spatial GEMM, tf32 mma.sync, CTA tile 128x256, warp tile 64x64,
// BK=32, cp.async double-buffered. Tensor-bound by design (smem traffic
// halved vs 32x64 warp tiles).
//   D[b][i][to] = relu( sum_kj AT[b][i][kj] * yT[b][to][kj] )
// ---------------------------------------------------------------------------
#define SBK    32
#define NTILE  (KJP_ / SBK)          // 94
#define BNX    256
#define A_STG  (128 * 36)            // floats per A stage
#define B_STG  (BNX * 36)            // floats per B stage

__global__ __launch_bounds__(256) void k_spatial_big(float* __restrict__ out)
{
    extern __shared__ float sm[];
    float* Asm = sm;                      // [2][128][36]
    float* Bsm = sm + 2 * A_STG;          // [2][256][36]

    const int b  = blockIdx.z;
    const int i0 = blockIdx.y * 128;
    const int n0 = blockIdx.x * BNX;

    const int tid  = threadIdx.x;
    const int lane = tid & 31;
    const int w    = tid >> 5;
    const int im   = (w & 1) * 64;        // warp m-origin (64-row strip)
    const int in_  = (w >> 1) * 64;       // warp n-origin (64-col strip)

    const float* __restrict__ atp = g_AT + ((size_t)b * MP_ + i0) * KJP_;
    const float* __restrict__ ytp = g_yT + ((size_t)b * TO_ + n0) * KJP_;

    float c[4][8][4];
    #pragma unroll
    for (int mt = 0; mt < 4; mt++)
        #pragma unroll
        for (int nt = 0; nt < 8; nt++)
            #pragma unroll
            for (int q = 0; q < 4; q++) c[mt][nt][q] = 0.f;

    const uint32_t as_base = smem_u32(Asm);
    const uint32_t bs_base = smem_u32(Bsm);

    // loader geometry: 16B chunks, 8 chunks per row of 32 floats
    const int ld_row = tid >> 3;          // 0..31 (+32*l)
    const int ld_c4  = (tid & 7) * 4;     // 0..28

    const int a_row  = lane & 15;
    const int a_col4 = (lane >> 4) * 4;
    const int b_row  = (lane & 7) + ((lane & 16) >> 1);
    const int b_col4 = ((lane >> 3) & 1) * 4;

    #define LOAD_TILE(p, stage) do {                                            \
        const uint32_t ao = as_base + (uint32_t)((stage) * A_STG * 4);          \
        const uint32_t bo = bs_base + (uint32_t)((stage) * B_STG * 4);          \
        _Pragma("unroll")                                                       \
        for (int l = 0; l < 4; l++) {                                           \
            const int row = ld_row + l * 32;                                    \
            cpasync16(ao + (uint32_t)((row * 36 + ld_c4) * 4),                  \
                      atp + (size_t)row * KJP_ + (p) + ld_c4);                  \
        }                                                                       \
        _Pragma("unroll")                                                       \
        for (int l = 0; l < 8; l++) {                                           \
            const int row = ld_row + l * 32;                                    \
            cpasync16(bo + (uint32_t)((row * 36 + ld_c4) * 4),                  \
                      ytp + (size_t)row * KJP_ + (p) + ld_c4);                  \
        }                                                                       \
        asm volatile("cp.async.commit_group;");                                 \
    } while (0)

    LOAD_TILE(0, 0);

    for (int pc = 0; pc < NTILE; pc++) {
        const int cur = pc & 1;
        asm volatile("cp.async.wait_group 0;");
        __syncthreads();

        if (pc + 1 < NTILE) LOAD_TILE((pc + 1) * SBK, cur ^ 1);

        const uint32_t abo = as_base + (uint32_t)(cur * A_STG * 4);
        const uint32_t bbo = bs_base + (uint32_t)(cur * B_STG * 4);

        #pragma unroll
        for (int ks = 0; ks < 4; ks++) {
            const int k0 = ks * 8;
            uint32_t a[4][4];
            #pragma unroll
            for (int mt = 0; mt < 4; mt++) {
                const uint32_t addr = abo +
                    (uint32_t)(((im + mt * 16 + a_row) * 36 + k0 + a_col4) * 4);
                asm volatile(
                    "ldmatrix.sync.aligned.m8n8.x4.shared.b16 {%0,%1,%2,%3}, [%4];"
                    : "=r"(a[mt][0]), "=r"(a[mt][1]), "=r"(a[mt][2]), "=r"(a[mt][3])
                    : "r"(addr));
            }
            uint32_t bb[8][2];
            #pragma unroll
            for (int nb = 0; nb < 4; nb++) {
                const uint32_t addr = bbo +
                    (uint32_t)(((in_ + nb * 16 + b_row) * 36 + k0 + b_col4) * 4);
                uint32_t r0, r1, r2, r3;
                asm volatile(
                    "ldmatrix.sync.aligned.m8n8.x4.shared.b16 {%0,%1,%2,%3}, [%4];"
                    : "=r"(r0), "=r"(r1), "=r"(r2), "=r"(r3)
                    : "r"(addr));
                bb[nb * 2][0] = r0;     bb[nb * 2][1] = r1;
                bb[nb * 2 + 1][0] = r2; bb[nb * 2 + 1][1] = r3;
            }
            #pragma unroll
            for (int mt = 0; mt < 4; mt++)
                #pragma unroll
                for (int nt = 0; nt < 8; nt++)
                    asm volatile(
                        "mma.sync.aligned.m16n8k8.row.col.f32.tf32.tf32.f32 "
                        "{%0,%1,%2,%3}, {%4,%5,%6,%7}, {%8,%9}, {%0,%1,%2,%3};"
                        : "+f"(c[mt][nt][0]), "+f"(c[mt][nt][1]),
                          "+f"(c[mt][nt][2]), "+f"(c[mt][nt][3])
                        : "r"(a[mt][0]), "r"(a[mt][1]), "r"(a[mt][2]), "r"(a[mt][3]),
                          "r"(bb[nt][0]), "r"(bb[nt][1]));
        }
        __syncthreads();
    }

    // Epilogue with fused relu. Warp n-extent is 64 and 64-aligned -> t const.
    const int gid = lane >> 2;
    const int tig = lane & 3;
    const int t   = (n0 + in_) >> 6;
    #pragma unroll
    for (int mt = 0; mt < 4; mt++) {
        #pragma unroll
        for (int half = 0; half < 2; half++) {
            const int i = i0 + im + mt * 16 + half * 8 + gid;
            if (i < N_) {
                float* __restrict__ dst =
                    out + (size_t)b * (T_ * N_ * OUT_) + (size_t)t * (N_ * OUT_) +
                    (size_t)i * OUT_;
                #pragma unroll
                for (int nt = 0; nt < 8; nt++) {
                    const int o = nt * 8 + tig * 2;
                    float2 v;
                    v.x = fmaxf(c[mt][nt][half * 2 + 0], 0.f);
                    v.y = fmaxf(c[mt][nt][half * 2 + 1], 0.f);
                    *(float2*)&dst[o] = v;
                }
            }
        }
    }
}

// ---------------------------------------------------------------------------
// Launch
// ---------------------------------------------------------------------------
extern "C" void kernel_launch(void* const* d_in, const int* in_sizes, int n_in,
                              void* d_out, int out_size)
{
    const float* x     = (const float*)d_in[0];
    const float* SAtt  = (const float*)d_in[1];
    const float* cheb  = (const float*)d_in[2];
    const float* Theta = (const float*)d_in[3];
    float* out = (float*)d_out;

    const int smem_big = 2 * (A_STG + B_STG) * sizeof(float);   // 110592 B
    cudaFuncSetAttribute(k_spatial_big,
                         cudaFuncAttributeMaxDynamicSharedMemorySize, smem_big);

    k_thetaT<<<1, 256>>>(Theta);
    k_featT_tc<<<dim3(8, 3, B_ * T_), 256>>>(x);
    k_buildA<<<dim3(12, 32), 256>>>(SAtt, cheb);
    k_spatial_big<<<dim3(TO_ / BNX, MP_ / 128, B_), 256, smem_big>>>(out);
}

// round 8
// speedup vs baseline: 1.9073x; 1.3293x over previous
#include <cuda_runtime.h>
#include <cuda_fp16.h>
#include <cstdint>

// Shapes (fixed by the problem)
#define B_   16
#define T_   12
#define N_   1000
#define F_   64
#define KC_  3
#define OUT_ 64

#define KJ_   3000            // contraction dim kj = k*1000 + j
#define KJP_  3008            // padded (mult of 32)
#define MP_   1024            // i padded
#define TO_   768             // t*64 + o

// Scratch (zero-initialized at module load; pad regions never written -> stay 0)
__device__ __align__(256) float  g_ThT[KC_ * OUT_ * F_];          // tf32
__device__ __align__(256) __half g_yT[(size_t)B_ * TO_ * KJP_];   // y  fp16
__device__ __align__(256) __half g_AT[(size_t)B_ * MP_ * KJP_];   // A  fp16

__device__ __forceinline__ float to_tf32(float v) {
    uint32_t u;
    asm("cvt.rna.tf32.f32 %0, %1;" : "=r"(u) : "f"(v));
    return __uint_as_float(u);
}

__device__ __forceinline__ void cpasync16(uint32_t dst, const void* src) {
    asm volatile("cp.async.cg.shared.global [%0], [%1], 16;" :: "r"(dst), "l"(src));
}

__device__ __forceinline__ uint32_t smem_u32(const void* p) {
    uint32_t a;
    asm("{ .reg .u64 t; cvta.to.shared.u64 t, %1; cvt.u32.u64 %0, t; }"
        : "=r"(a) : "l"(p));
    return a;
}

// ---------------------------------------------------------------------------
// Kernel 0: ThT[(k*64+o)][f] = tf32(Theta[k,f,o])
// ---------------------------------------------------------------------------
__global__ __launch_bounds__(256) void k_thetaT(const float* __restrict__ Theta)
{
    for (int idx = threadIdx.x; idx < KC_ * OUT_ * F_; idx += 256) {
        const int f  = idx & 63;
        const int ko = idx >> 6;
        const int k  = ko >> 6;
        const int o  = ko & 63;
        g_ThT[idx] = to_tf32(Theta[(k * F_ + f) * OUT_ + o]);
    }
}

// ---------------------------------------------------------------------------
// Kernel 1: feature transform (mma.sync tf32), fp16 transposed output
//   y[b][t*64+o][k*1000+j] = sum_f ThT[(k*64+o)][f] * x[b,t,j,f]
// ---------------------------------------------------------------------------
__global__ __launch_bounds__(256) void k_featT_tc(const float* __restrict__ x)
{
    __shared__ float As[64][36];
    __shared__ float Bs[128][36];

    const int j0 = blockIdx.x * 128;
    const int m0 = blockIdx.y * 64;
    const int bt = blockIdx.z;
    const int b  = bt / T_;
    const int t  = bt % T_;

    const int tid  = threadIdx.x;
    const int lane = tid & 31;
    const int w    = tid >> 5;
    const int wm   = (w & 1) * 32;
    const int wn   = (w >> 1) * 32;

    const float* __restrict__ xp = x + (size_t)bt * N_ * F_;

    float c[2][4][4];
    #pragma unroll
    for (int mt = 0; mt < 2; mt++)
        #pragma unroll
        for (int nt = 0; nt < 4; nt++)
            #pragma unroll
            for (int q = 0; q < 4; q++) c[mt][nt][q] = 0.f;

    const uint32_t as_base = smem_u32(&As[0][0]);
    const uint32_t bs_base = smem_u32(&Bs[0][0]);

    const int a_row  = lane & 15;
    const int a_col4 = (lane >> 4) * 4;
    const int b_row  = (lane & 7) + ((lane & 16) >> 1);
    const int b_col4 = ((lane >> 3) & 1) * 4;

    #pragma unroll
    for (int kt = 0; kt < 2; kt++) {
        const int f0 = kt * 32;
        #pragma unroll
        for (int l = 0; l < 2; l++) {
            int idx = tid + l * 256;
            int row = idx >> 3, c4 = (idx & 7) * 4;
            *(float4*)&As[row][c4] = *(const float4*)&g_ThT[(m0 + row) * F_ + f0 + c4];
        }
        #pragma unroll
        for (int l = 0; l < 4; l++) {
            int idx = tid + l * 256;
            int row = idx >> 3, c4 = (idx & 7) * 4;
            float4 v;
            if (j0 + row < N_) {
                v = *(const float4*)&xp[(size_t)(j0 + row) * F_ + f0 + c4];
                v.x = to_tf32(v.x); v.y = to_tf32(v.y);
                v.z = to_tf32(v.z); v.w = to_tf32(v.w);
            } else {
                v = make_float4(0.f, 0.f, 0.f, 0.f);
            }
            *(float4*)&Bs[row][c4] = v;
        }
        __syncthreads();

        #pragma unroll
        for (int ks = 0; ks < 4; ks++) {
            const int k0 = ks * 8;
            uint32_t a[2][4];
            #pragma unroll
            for (int mt = 0; mt < 2; mt++) {
                uint32_t addr = as_base +
                    (uint32_t)(((wm + mt * 16 + a_row) * 36 + k0 + a_col4) * 4);
                asm volatile(
                    "ldmatrix.sync.aligned.m8n8.x4.shared.b16 {%0,%1,%2,%3}, [%4];"
                    : "=r"(a[mt][0]), "=r"(a[mt][1]), "=r"(a[mt][2]), "=r"(a[mt][3])
                    : "r"(addr));
            }
            uint32_t bb[4][2];
            #pragma unroll
            for (int nb = 0; nb < 2; nb++) {
                uint32_t addr = bs_base +
                    (uint32_t)(((wn + nb * 16 + b_row) * 36 + k0 + b_col4) * 4);
                uint32_t r0, r1, r2, r3;
                asm volatile(
                    "ldmatrix.sync.aligned.m8n8.x4.shared.b16 {%0,%1,%2,%3}, [%4];"
                    : "=r"(r0), "=r"(r1), "=r"(r2), "=r"(r3)
                    : "r"(addr));
                bb[nb * 2][0] = r0;     bb[nb * 2][1] = r1;
                bb[nb * 2 + 1][0] = r2; bb[nb * 2 + 1][1] = r3;
            }
            #pragma unroll
            for (int mt = 0; mt < 2; mt++)
                #pragma unroll
                for (int nt = 0; nt < 4; nt++)
                    asm volatile(
                        "mma.sync.aligned.m16n8k8.row.col.f32.tf32.tf32.f32 "
                        "{%0,%1,%2,%3}, {%4,%5,%6,%7}, {%8,%9}, {%0,%1,%2,%3};"
                        : "+f"(c[mt][nt][0]), "+f"(c[mt][nt][1]),
                          "+f"(c[mt][nt][2]), "+f"(c[mt][nt][3])
                        : "r"(a[mt][0]), "r"(a[mt][1]), "r"(a[mt][2]), "r"(a[mt][3]),
                          "r"(bb[nt][0]), "r"(bb[nt][1]));
        }
        __syncthreads();
    }

    // Epilogue: write fp16, kj-contiguous
    const int gid = lane >> 2;
    const int tig = lane & 3;
    #pragma unroll
    for (int mt = 0; mt < 2; mt++) {
        #pragma unroll
        for (int half = 0; half < 2; half++) {
            const int ko = m0 + wm + mt * 16 + half * 8 + gid;
            const int k  = ko >> 6;
            const int o  = ko & 63;
            __half* __restrict__ dst =
                g_yT + ((size_t)b * TO_ + t * OUT_ + o) * KJP_ + (size_t)k * N_;
            #pragma unroll
            for (int nt = 0; nt < 4; nt++) {
                const int j = j0 + wn + nt * 8 + tig * 2;
                if (j < N_) {
                    __half2 v;
                    v.x = __float2half_rn(c[mt][nt][half * 2 + 0]);
                    v.y = __float2half_rn(c[mt][nt][half * 2 + 1]);
                    *(__half2*)&dst[j] = v;
                }
            }
        }
    }
}

// ---------------------------------------------------------------------------
// Kernel 2: AT[b][i][kj] = fp16( cheb[kj,i] * SAtt[b, kj%1000, i] )
// cheb cached in registers; b loop inside block.
// ---------------------------------------------------------------------------
__global__ __launch_bounds__(256) void k_buildA(
    const float* __restrict__ SAtt,
    const float* __restrict__ cheb)
{
    __shared__ float buf[256][33];
    const int i0   = blockIdx.y * 32;
    const int kjc  = blockIdx.x * 256;
    const int lane = threadIdx.x & 31;
    const int w    = threadIdx.x >> 5;
    const int i    = i0 + lane;

    float ch[32];
    int   jj[32];
    bool  ok[32];
    #pragma unroll 8
    for (int r = 0; r < 32; r++) {
        const int kj = kjc + w * 32 + r;
        ok[r] = (kj < KJ_) && (i < N_);
        const int k = (kj >= 2000) ? 2 : (kj >= 1000 ? 1 : 0);
        jj[r] = (kj < KJ_) ? (kj - k * 1000) : 0;
        ch[r] = ok[r] ? __ldg(cheb + (size_t)kj * N_ + i) : 0.f;
    }

    for (int b = 0; b < B_; b++) {
        const float* __restrict__ sb = SAtt + (size_t)b * N_ * N_;
        #pragma unroll 8
        for (int r = 0; r < 32; r++) {
            float v = 0.f;
            if (ok[r]) v = ch[r] * __ldg(sb + (size_t)jj[r] * N_ + i);
            buf[w * 32 + r][lane] = v;
        }
        __syncthreads();

        #pragma unroll
        for (int rr = 0; rr < 4; rr++) {
            const int iw = i0 + w * 4 + rr;
            if (iw < N_) {
                __half* __restrict__ outp = g_AT + ((size_t)b * MP_ + iw) * KJP_;
                #pragma unroll
                for (int c = 0; c < 8; c++) {
                    const int kj = kjc + c * 32 + lane;
                    if (kj < KJ_)
                        outp[kj] = __float2half_rn(buf[c * 32 + lane][w * 4 + rr]);
                }
            }
        }
        __syncthreads();
    }
}

// ---------------------------------------------------------------------------
// Kernel 3: spatial GEMM, fp16 m16n8k16 mma (fp32 accum), BK=32,
// cp.async double-buffered, one sync per tile, 2 CTAs/SM.
//   D[b][i][to] = relu( sum_kj AT[b][i][kj] * yT[b][to][kj] )
// ---------------------------------------------------------------------------
#define SBK    32
#define NTILE  (KJP_ / SBK)          // 94
#define ROWH   40                    // halfs per smem row (80B, pad)
#define PART_H (128 * ROWH)          // halfs per operand per stage

__global__ __launch_bounds__(256, 2) void k_spatial_fp16(float* __restrict__ out)
{
    extern __shared__ __half sm[];
    // layout: [stage][operand 0..1 = A, B][128][40]

    const int b  = blockIdx.z;
    const int i0 = blockIdx.y * 128;
    const int n0 = blockIdx.x * 128;

    const int tid  = threadIdx.x;
    const int lane = tid & 31;
    const int w    = tid >> 5;
    const int im   = (w & 3) * 32;
    const int in_  = (w >> 2) * 64;

    const __half* __restrict__ pA = g_AT + ((size_t)b * MP_ + i0) * KJP_;
    const __half* __restrict__ pB = g_yT + ((size_t)b * TO_ + n0) * KJP_;

    float c[2][8][4];
    #pragma unroll
    for (int mt = 0; mt < 2; mt++)
        #pragma unroll
        for (int nt = 0; nt < 8; nt++)
            #pragma unroll
            for (int q = 0; q < 4; q++) c[mt][nt][q] = 0.f;

    const uint32_t s_base = smem_u32(sm);

    // loader: per operand 512 16B-chunks, 2 per thread
    const int ld_row = tid >> 1;            // 0..127
    const int ld_h0  = (tid & 1) * 16;      // half-offset 0 or 16

    // fragment geometry (proven in R6)
    const int a_row = lane & 15;
    const int a_k8  = lane >> 4;
    const int b_row = (lane & 7) + ((lane & 16) >> 1);
    const int b_k8  = (lane >> 3) & 1;

    #define LOAD_TILE(p, s) do {                                                \
        const uint32_t sb_ = s_base + (uint32_t)((s) * 2 * PART_H * 2);         \
        const size_t go = (size_t)ld_row * KJP_ + (p) + ld_h0;                  \
        const uint32_t so = (uint32_t)(ld_row * ROWH + ld_h0) * 2;              \
        cpasync16(sb_ + so,                    pA + go);                        \
        cpasync16(sb_ + so + 16,               pA + go + 8);                    \
        cpasync16(sb_ + PART_H * 2 + so,       pB + go);                        \
        cpasync16(sb_ + PART_H * 2 + so + 16,  pB + go + 8);                    \
        asm volatile("cp.async.commit_group;");                                 \
    } while (0)

    LOAD_TILE(0, 0);

    for (int pc = 0; pc < NTILE; pc++) {
        const int cur = pc & 1;
        asm volatile("cp.async.wait_group 0;");
        __syncthreads();

        if (pc + 1 < NTILE) LOAD_TILE((pc + 1) * SBK, cur ^ 1);

        const uint32_t st = s_base + (uint32_t)(cur * 2 * PART_H * 2);
        const uint32_t sA = st;
        const uint32_t sB = st + PART_H * 2;

        #pragma unroll
        for (int ks = 0; ks < 2; ks++) {
            const int kb = ks * 16;

            uint32_t a[2][4];
            #pragma unroll
            for (int mt = 0; mt < 2; mt++) {
                const uint32_t off =
                    (uint32_t)(((im + mt * 16 + a_row) * ROWH + kb + a_k8 * 8) * 2);
                asm volatile(
                    "ldmatrix.sync.aligned.m8n8.x4.shared.b16 {%0,%1,%2,%3}, [%4];"
                    : "=r"(a[mt][0]), "=r"(a[mt][1]), "=r"(a[mt][2]), "=r"(a[mt][3])
                    : "r"(sA + off));
            }
            uint32_t bb[8][2];
            #pragma unroll
            for (int nb = 0; nb < 4; nb++) {
                const uint32_t off =
                    (uint32_t)(((in_ + nb * 16 + b_row) * ROWH + kb + b_k8 * 8) * 2);
                uint32_t r0, r1, r2, r3;
                asm volatile(
                    "ldmatrix.sync.aligned.m8n8.x4.shared.b16 {%0,%1,%2,%3}, [%4];"
                    : "=r"(r0), "=r"(r1), "=r"(r2), "=r"(r3)
                    : "r"(sB + off));
                bb[nb * 2][0] = r0;     bb[nb * 2][1] = r1;
                bb[nb * 2 + 1][0] = r2; bb[nb * 2 + 1][1] = r3;
            }
            #pragma unroll
            for (int mt = 0; mt < 2; mt++)
                #pragma unroll
                for (int nt = 0; nt < 8; nt++)
                    asm volatile(
                        "mma.sync.aligned.m16n8k16.row.col.f32.f16.f16.f32 "
                        "{%0,%1,%2,%3}, {%4,%5,%6,%7}, {%8,%9}, {%0,%1,%2,%3};"
                        : "+f"(c[mt][nt][0]), "+f"(c[mt][nt][1]),
                          "+f"(c[mt][nt][2]), "+f"(c[mt][nt][3])
                        : "r"(a[mt][0]), "r"(a[mt][1]), "r"(a[mt][2]), "r"(a[mt][3]),
                          "r"(bb[nt][0]), "r"(bb[nt][1]));
        }
        __syncthreads();
    }

    // Epilogue with fused relu
    const int gid = lane >> 2;
    const int tig = lane & 3;
    #pragma unroll
    for (int mt = 0; mt < 2; mt++) {
        #pragma unroll
        for (int half = 0; half < 2; half++) {
            const int i = i0 + im + mt * 16 + half * 8 + gid;
            if (i < N_) {
                #pragma unroll
                for (int nt = 0; nt < 8; nt++) {
                    const int to = n0 + in_ + nt * 8 + tig * 2;
                    const int t  = to >> 6;
                    const int o  = to & 63;
                    float2 v;
                    v.x = fmaxf(c[mt][nt][half * 2 + 0], 0.f);
                    v.y = fmaxf(c[mt][nt][half * 2 + 1], 0.f);
                    *(float2*)&out[(size_t)b * (T_ * N_ * OUT_) +
                                   (size_t)t * (N_ * OUT_) +
                                   (size_t)i * OUT_ + o] = v;
                }
            }
        }
    }
}

// ---------------------------------------------------------------------------
// Launch
// ---------------------------------------------------------------------------
extern "C" void kernel_launch(void* const* d_in, const int* in_sizes, int n_in,
                              void* d_out, int out_size)
{
    const float* x     = (const float*)d_in[0];
    const float* SAtt  = (const float*)d_in[1];
    const float* cheb  = (const float*)d_in[2];
    const float* Theta = (const float*)d_in[3];
    float* out = (float*)d_out;

    const int smem_sp = 2 * 2 * PART_H * 2;   // 2 stages x 2 operands x 10240B = 40960
    cudaFuncSetAttribute(k_spatial_fp16,
                         cudaFuncAttributeMaxDynamicSharedMemorySize, smem_sp);

    k_thetaT<<<1, 256>>>(Theta);
    k_featT_tc<<<dim3(8, 3, B_ * T_), 256>>>(x);
    k_buildA<<<dim3(12, 32), 256>>>(SAtt, cheb);
    k_spatial_fp16<<<dim3(TO_ / 128, MP_ / 128, B_), 256, smem_sp>>>(out);
}

// round 9
// speedup vs baseline: 1.9605x; 1.0279x over previous
#include <cuda_runtime.h>
#include <cuda_fp16.h>
#include <cstdint>

// Shapes (fixed by the problem)
#define B_   16
#define T_   12
#define N_   1000
#define F_   64
#define KC_  3
#define OUT_ 64

#define KJ_   3000            // contraction dim kj = k*1000 + j
#define KJP_  3008            // padded (mult of 32)
#define MP_   1024            // i padded
#define TO_   768             // t*64 + o

// Scratch (zero-initialized at module load; pad regions never written -> stay 0)
__device__ __align__(256) float  g_ThT[KC_ * OUT_ * F_];          // tf32
__device__ __align__(256) __half g_yT[(size_t)B_ * TO_ * KJP_];   // y  fp16
__device__ __align__(256) __half g_AT[(size_t)B_ * MP_ * KJP_];   // A  fp16

__device__ __forceinline__ float to_tf32(float v) {
    uint32_t u;
    asm("cvt.rna.tf32.f32 %0, %1;" : "=r"(u) : "f"(v));
    return __uint_as_float(u);
}

__device__ __forceinline__ void cpasync16(uint32_t dst, const void* src) {
    asm volatile("cp.async.cg.shared.global [%0], [%1], 16;" :: "r"(dst), "l"(src));
}

__device__ __forceinline__ uint32_t smem_u32(const void* p) {
    uint32_t a;
    asm("{ .reg .u64 t; cvta.to.shared.u64 t, %1; cvt.u32.u64 %0, t; }"
        : "=r"(a) : "l"(p));
    return a;
}

// ---------------------------------------------------------------------------
// Kernel 0: ThT[(k*64+o)][f] = tf32(Theta[k,f,o])
// ---------------------------------------------------------------------------
__global__ __launch_bounds__(256) void k_thetaT(const float* __restrict__ Theta)
{
    for (int idx = threadIdx.x; idx < KC_ * OUT_ * F_; idx += 256) {
        const int f  = idx & 63;
        const int ko = idx >> 6;
        const int k  = ko >> 6;
        const int o  = ko & 63;
        g_ThT[idx] = to_tf32(Theta[(k * F_ + f) * OUT_ + o]);
    }
}

// ---------------------------------------------------------------------------
// Kernel 1: feature transform (mma.sync tf32), fp16 transposed output
//   y[b][t*64+o][k*1000+j] = sum_f ThT[(k*64+o)][f] * x[b,t,j,f]
// ---------------------------------------------------------------------------
__global__ __launch_bounds__(256) void k_featT_tc(const float* __restrict__ x)
{
    __shared__ float As[64][36];
    __shared__ float Bs[128][36];

    const int j0 = blockIdx.x * 128;
    const int m0 = blockIdx.y * 64;
    const int bt = blockIdx.z;
    const int b  = bt / T_;
    const int t  = bt % T_;

    const int tid  = threadIdx.x;
    const int lane = tid & 31;
    const int w    = tid >> 5;
    const int wm   = (w & 1) * 32;
    const int wn   = (w >> 1) * 32;

    const float* __restrict__ xp = x + (size_t)bt * N_ * F_;

    float c[2][4][4];
    #pragma unroll
    for (int mt = 0; mt < 2; mt++)
        #pragma unroll
        for (int nt = 0; nt < 4; nt++)
            #pragma unroll
            for (int q = 0; q < 4; q++) c[mt][nt][q] = 0.f;

    const uint32_t as_base = smem_u32(&As[0][0]);
    const uint32_t bs_base = smem_u32(&Bs[0][0]);

    const int a_row  = lane & 15;
    const int a_col4 = (lane >> 4) * 4;
    const int b_row  = (lane & 7) + ((lane & 16) >> 1);
    const int b_col4 = ((lane >> 3) & 1) * 4;

    #pragma unroll
    for (int kt = 0; kt < 2; kt++) {
        const int f0 = kt * 32;
        #pragma unroll
        for (int l = 0; l < 2; l++) {
            int idx = tid + l * 256;
            int row = idx >> 3, c4 = (idx & 7) * 4;
            *(float4*)&As[row][c4] = *(const float4*)&g_ThT[(m0 + row) * F_ + f0 + c4];
        }
        #pragma unroll
        for (int l = 0; l < 4; l++) {
            int idx = tid + l * 256;
            int row = idx >> 3, c4 = (idx & 7) * 4;
            float4 v;
            if (j0 + row < N_) {
                v = *(const float4*)&xp[(size_t)(j0 + row) * F_ + f0 + c4];
                v.x = to_tf32(v.x); v.y = to_tf32(v.y);
                v.z = to_tf32(v.z); v.w = to_tf32(v.w);
            } else {
                v = make_float4(0.f, 0.f, 0.f, 0.f);
            }
            *(float4*)&Bs[row][c4] = v;
        }
        __syncthreads();

        #pragma unroll
        for (int ks = 0; ks < 4; ks++) {
            const int k0 = ks * 8;
            uint32_t a[2][4];
            #pragma unroll
            for (int mt = 0; mt < 2; mt++) {
                uint32_t addr = as_base +
                    (uint32_t)(((wm + mt * 16 + a_row) * 36 + k0 + a_col4) * 4);
                asm volatile(
                    "ldmatrix.sync.aligned.m8n8.x4.shared.b16 {%0,%1,%2,%3}, [%4];"
                    : "=r"(a[mt][0]), "=r"(a[mt][1]), "=r"(a[mt][2]), "=r"(a[mt][3])
                    : "r"(addr));
            }
            uint32_t bb[4][2];
            #pragma unroll
            for (int nb = 0; nb < 2; nb++) {
                uint32_t addr = bs_base +
                    (uint32_t)(((wn + nb * 16 + b_row) * 36 + k0 + b_col4) * 4);
                uint32_t r0, r1, r2, r3;
                asm volatile(
                    "ldmatrix.sync.aligned.m8n8.x4.shared.b16 {%0,%1,%2,%3}, [%4];"
                    : "=r"(r0), "=r"(r1), "=r"(r2), "=r"(r3)
                    : "r"(addr));
                bb[nb * 2][0] = r0;     bb[nb * 2][1] = r1;
                bb[nb * 2 + 1][0] = r2; bb[nb * 2 + 1][1] = r3;
            }
            #pragma unroll
            for (int mt = 0; mt < 2; mt++)
                #pragma unroll
                for (int nt = 0; nt < 4; nt++)
                    asm volatile(
                        "mma.sync.aligned.m16n8k8.row.col.f32.tf32.tf32.f32 "
                        "{%0,%1,%2,%3}, {%4,%5,%6,%7}, {%8,%9}, {%0,%1,%2,%3};"
                        : "+f"(c[mt][nt][0]), "+f"(c[mt][nt][1]),
                          "+f"(c[mt][nt][2]), "+f"(c[mt][nt][3])
                        : "r"(a[mt][0]), "r"(a[mt][1]), "r"(a[mt][2]), "r"(a[mt][3]),
                          "r"(bb[nt][0]), "r"(bb[nt][1]));
        }
        __syncthreads();
    }

    // Epilogue: write fp16, kj-contiguous
    const int gid = lane >> 2;
    const int tig = lane & 3;
    #pragma unroll
    for (int mt = 0; mt < 2; mt++) {
        #pragma unroll
        for (int half = 0; half < 2; half++) {
            const int ko = m0 + wm + mt * 16 + half * 8 + gid;
            const int k  = ko >> 6;
            const int o  = ko & 63;
            __half* __restrict__ dst =
                g_yT + ((size_t)b * TO_ + t * OUT_ + o) * KJP_ + (size_t)k * N_;
            #pragma unroll
            for (int nt = 0; nt < 4; nt++) {
                const int j = j0 + wn + nt * 8 + tig * 2;
                if (j < N_) {
                    __half2 v;
                    v.x = __float2half_rn(c[mt][nt][half * 2 + 0]);
                    v.y = __float2half_rn(c[mt][nt][half * 2 + 1]);
                    *(__half2*)&dst[j] = v;
                }
            }
        }
    }
}

// ---------------------------------------------------------------------------
// Kernel 2: AT[b][i][kj] = fp16( cheb[kj,i] * SAtt[b, kj%1000, i] )
// cheb cached in registers; b loop inside block.
// ---------------------------------------------------------------------------
__global__ __launch_bounds__(256) void k_buildA(
    const float* __restrict__ SAtt,
    const float* __restrict__ cheb)
{
    __shared__ float buf[256][33];
    const int i0   = blockIdx.y * 32;
    const int kjc  = blockIdx.x * 256;
    const int lane = threadIdx.x & 31;
    const int w    = threadIdx.x >> 5;
    const int i    = i0 + lane;

    float ch[32];
    int   jj[32];
    bool  ok[32];
    #pragma unroll 8
    for (int r = 0; r < 32; r++) {
        const int kj = kjc + w * 32 + r;
        ok[r] = (kj < KJ_) && (i < N_);
        const int k = (kj >= 2000) ? 2 : (kj >= 1000 ? 1 : 0);
        jj[r] = (kj < KJ_) ? (kj - k * 1000) : 0;
        ch[r] = ok[r] ? __ldg(cheb + (size_t)kj * N_ + i) : 0.f;
    }

    for (int b = 0; b < B_; b++) {
        const float* __restrict__ sb = SAtt + (size_t)b * N_ * N_;
        #pragma unroll 8
        for (int r = 0; r < 32; r++) {
            float v = 0.f;
            if (ok[r]) v = ch[r] * __ldg(sb + (size_t)jj[r] * N_ + i);
            buf[w * 32 + r][lane] = v;
        }
        __syncthreads();

        #pragma unroll
        for (int rr = 0; rr < 4; rr++) {
            const int iw = i0 + w * 4 + rr;
            if (iw < N_) {
                __half* __restrict__ outp = g_AT + ((size_t)b * MP_ + iw) * KJP_;
                #pragma unroll
                for (int c = 0; c < 8; c++) {
                    const int kj = kjc + c * 32 + lane;
                    if (kj < KJ_)
                        outp[kj] = __float2half_rn(buf[c * 32 + lane][w * 4 + rr]);
                }
            }
        }
        __syncthreads();
    }
}

// ---------------------------------------------------------------------------
// Kernel 3: spatial GEMM, fp16 m16n8k16, CTA tile 128x256, warp tile 64x64,
// BK=32, cp.async double-buffered, one sync per tile.
//   D[b][i][to] = relu( sum_kj AT[b][i][kj] * yT[b][to][kj] )
// ---------------------------------------------------------------------------
#define SBK    32
#define NTILE  (KJP_ / SBK)          // 94
#define BNX    256
#define ROWH   40                    // halfs per smem row (80B, padded)
#define A_STGH (128 * ROWH)          // halfs per A stage
#define B_STGH (BNX * ROWH)          // halfs per B stage

__global__ __launch_bounds__(256) void k_spatial_fp16b(float* __restrict__ out)
{
    extern __shared__ __half sm[];
    __half* Asm = sm;                     // [2][128][40]
    __half* Bsm = sm + 2 * A_STGH;        // [2][256][40]

    const int b  = blockIdx.z;
    const int i0 = blockIdx.y * 128;
    const int n0 = blockIdx.x * BNX;

    const int tid  = threadIdx.x;
    const int lane = tid & 31;
    const int w    = tid >> 5;
    const int im   = (w & 1) * 64;        // warp m-origin
    const int in_  = (w >> 1) * 64;       // warp n-origin

    const __half* __restrict__ pA = g_AT + ((size_t)b * MP_ + i0) * KJP_;
    const __half* __restrict__ pB = g_yT + ((size_t)b * TO_ + n0) * KJP_;

    float c[4][8][4];
    #pragma unroll
    for (int mt = 0; mt < 4; mt++)
        #pragma unroll
        for (int nt = 0; nt < 8; nt++)
            #pragma unroll
            for (int q = 0; q < 4; q++) c[mt][nt][q] = 0.f;

    const uint32_t as_base = smem_u32(Asm);
    const uint32_t bs_base = smem_u32(Bsm);

    // loader: rows of 32 halfs = 4 x 16B chunks; thread -> (row, chunk)
    const int ld_row = tid >> 2;          // 0..63
    const int ld_h0  = (tid & 3) * 8;     // half offset 0,8,16,24

    // fragment geometry (proven in R8)
    const int a_row = lane & 15;
    const int a_k8  = lane >> 4;
    const int b_row = (lane & 7) + ((lane & 16) >> 1);
    const int b_k8  = (lane >> 3) & 1;

    #define LOAD_TILE(p, s) do {                                                \
        const uint32_t ao = as_base + (uint32_t)((s) * A_STGH * 2);             \
        const uint32_t bo = bs_base + (uint32_t)((s) * B_STGH * 2);             \
        _Pragma("unroll")                                                       \
        for (int l = 0; l < 2; l++) {                                           \
            const int row = ld_row + l * 64;                                    \
            cpasync16(ao + (uint32_t)((row * ROWH + ld_h0) * 2),                \
                      pA + (size_t)row * KJP_ + (p) + ld_h0);                   \
        }                                                                       \
        _Pragma("unroll")                                                       \
        for (int l = 0; l < 4; l++) {                                           \
            const int row = ld_row + l * 64;                                    \
            cpasync16(bo + (uint32_t)((row * ROWH + ld_h0) * 2),                \
                      pB + (size_t)row * KJP_ + (p) + ld_h0);                   \
        }                                                                       \
        asm volatile("cp.async.commit_group;");                                 \
    } while (0)

    LOAD_TILE(0, 0);

    for (int pc = 0; pc < NTILE; pc++) {
        const int cur = pc & 1;
        asm volatile("cp.async.wait_group 0;");
        __syncthreads();

        if (pc + 1 < NTILE) LOAD_TILE((pc + 1) * SBK, cur ^ 1);

        const uint32_t sA = as_base + (uint32_t)(cur * A_STGH * 2);
        const uint32_t sB = bs_base + (uint32_t)(cur * B_STGH * 2);

        #pragma unroll
        for (int ks = 0; ks < 2; ks++) {
            const int kb = ks * 16;

            uint32_t a[4][4];
            #pragma unroll
            for (int mt = 0; mt < 4; mt++) {
                const uint32_t off =
                    (uint32_t)(((im + mt * 16 + a_row) * ROWH + kb + a_k8 * 8) * 2);
                asm volatile(
                    "ldmatrix.sync.aligned.m8n8.x4.shared.b16 {%0,%1,%2,%3}, [%4];"
                    : "=r"(a[mt][0]), "=r"(a[mt][1]), "=r"(a[mt][2]), "=r"(a[mt][3])
                    : "r"(sA + off));
            }
            uint32_t bb[8][2];
            #pragma unroll
            for (int nb = 0; nb < 4; nb++) {
                const uint32_t off =
                    (uint32_t)(((in_ + nb * 16 + b_row) * ROWH + kb + b_k8 * 8) * 2);
                uint32_t r0, r1, r2, r3;
                asm volatile(
                    "ldmatrix.sync.aligned.m8n8.x4.shared.b16 {%0,%1,%2,%3}, [%4];"
                    : "=r"(r0), "=r"(r1), "=r"(r2), "=r"(r3)
                    : "r"(sB + off));
                bb[nb * 2][0] = r0;     bb[nb * 2][1] = r1;
                bb[nb * 2 + 1][0] = r2; bb[nb * 2 + 1][1] = r3;
            }
            #pragma unroll
            for (int mt = 0; mt < 4; mt++)
                #pragma unroll
                for (int nt = 0; nt < 8; nt++)
                    asm volatile(
                        "mma.sync.aligned.m16n8k16.row.col.f32.f16.f16.f32 "
                        "{%0,%1,%2,%3}, {%4,%5,%6,%7}, {%8,%9}, {%0,%1,%2,%3};"
                        : "+f"(c[mt][nt][0]), "+f"(c[mt][nt][1]),
                          "+f"(c[mt][nt][2]), "+f"(c[mt][nt][3])
                        : "r"(a[mt][0]), "r"(a[mt][1]), "r"(a[mt][2]), "r"(a[mt][3]),
                          "r"(bb[nt][0]), "r"(bb[nt][1]));
        }
        __syncthreads();
    }

    // Epilogue with fused relu; warp n-extent 64-aligned -> t const per warp
    const int gid = lane >> 2;
    const int tig = lane & 3;
    const int t   = (n0 + in_) >> 6;
    #pragma unroll
    for (int mt = 0; mt < 4; mt++) {
        #pragma unroll
        for (int half = 0; half < 2; half++) {
            const int i = i0 + im + mt * 16 + half * 8 + gid;
            if (i < N_) {
                float* __restrict__ dst =
                    out + (size_t)b * (T_ * N_ * OUT_) + (size_t)t * (N_ * OUT_) +
                    (size_t)i * OUT_;
                #pragma unroll
                for (int nt = 0; nt < 8; nt++) {
                    const int o = nt * 8 + tig * 2;
                    float2 v;
                    v.x = fmaxf(c[mt][nt][half * 2 + 0], 0.f);
                    v.y = fmaxf(c[mt][nt][half * 2 + 1], 0.f);
                    *(float2*)&dst[o] = v;
                }
            }
        }
    }
}

// ---------------------------------------------------------------------------
// Launch
// ---------------------------------------------------------------------------
extern "C" void kernel_launch(void* const* d_in, const int* in_sizes, int n_in,
                              void* d_out, int out_size)
{
    const float* x     = (const float*)d_in[0];
    const float* SAtt  = (const float*)d_in[1];
    const float* cheb  = (const float*)d_in[2];
    const float* Theta = (const float*)d_in[3];
    float* out = (float*)d_out;

    const int smem_sp = 2 * (A_STGH + B_STGH) * 2;   // 61440 B
    cudaFuncSetAttribute(k_spatial_fp16b,
                         cudaFuncAttributeMaxDynamicSharedMemorySize, smem_sp);

    k_thetaT<<<1, 256>>>(Theta);
    k_featT_tc<<<dim3(8, 3, B_ * T_), 256>>>(x);
    k_buildA<<<dim3(12, 32), 256>>>(SAtt, cheb);
    k_spatial_fp16b<<<dim3(TO_ / BNX, MP_ / 128, B_), 256, smem_sp>>>(out);
}

// round 10
// speedup vs baseline: 2.0030x; 1.0217x over previous
#include <cuda_runtime.h>
#include <cuda_fp16.h>
#include <cstdint>

// Shapes (fixed by the problem)
#define B_   16
#define T_   12
#define N_   1000
#define F_   64
#define KC_  3
#define OUT_ 64

#define KJ_   3000            // contraction dim kj = k*1000 + j
#define KJP_  3008            // padded (mult of 32)
#define MP_   1024            // i padded
#define TO_   768             // t*64 + o

// Scratch (zero-initialized at module load; pad regions never written -> stay 0)
__device__ __align__(256) float  g_ThT[KC_ * OUT_ * F_];          // tf32
__device__ __align__(256) __half g_yT[(size_t)B_ * TO_ * KJP_];   // y  fp16
__device__ __align__(256) __half g_AT[(size_t)B_ * MP_ * KJP_];   // A  fp16

__device__ __forceinline__ float to_tf32(float v) {
    uint32_t u;
    asm("cvt.rna.tf32.f32 %0, %1;" : "=r"(u) : "f"(v));
    return __uint_as_float(u);
}

__device__ __forceinline__ void cpasync16(uint32_t dst, const void* src) {
    asm volatile("cp.async.cg.shared.global [%0], [%1], 16;" :: "r"(dst), "l"(src));
}

__device__ __forceinline__ uint32_t smem_u32(const void* p) {
    uint32_t a;
    asm("{ .reg .u64 t; cvta.to.shared.u64 t, %1; cvt.u32.u64 %0, t; }"
        : "=r"(a) : "l"(p));
    return a;
}

// ---------------------------------------------------------------------------
// Kernel 0: ThT[(k*64+o)][f] = tf32(Theta[k,f,o])
// ---------------------------------------------------------------------------
__global__ __launch_bounds__(256) void k_thetaT(const float* __restrict__ Theta)
{
    for (int idx = threadIdx.x; idx < KC_ * OUT_ * F_; idx += 256) {
        const int f  = idx & 63;
        const int ko = idx >> 6;
        const int k  = ko >> 6;
        const int o  = ko & 63;
        g_ThT[idx] = to_tf32(Theta[(k * F_ + f) * OUT_ + o]);
    }
}

// ---------------------------------------------------------------------------
// Kernel 1: feature transform (mma.sync tf32), fp16 transposed output
//   y[b][t*64+o][k*1000+j] = sum_f ThT[(k*64+o)][f] * x[b,t,j,f]
// ---------------------------------------------------------------------------
__global__ __launch_bounds__(256) void k_featT_tc(const float* __restrict__ x)
{
    __shared__ float As[64][36];
    __shared__ float Bs[128][36];

    const int j0 = blockIdx.x * 128;
    const int m0 = blockIdx.y * 64;
    const int bt = blockIdx.z;
    const int b  = bt / T_;
    const int t  = bt % T_;

    const int tid  = threadIdx.x;
    const int lane = tid & 31;
    const int w    = tid >> 5;
    const int wm   = (w & 1) * 32;
    const int wn   = (w >> 1) * 32;

    const float* __restrict__ xp = x + (size_t)bt * N_ * F_;

    float c[2][4][4];
    #pragma unroll
    for (int mt = 0; mt < 2; mt++)
        #pragma unroll
        for (int nt = 0; nt < 4; nt++)
            #pragma unroll
            for (int q = 0; q < 4; q++) c[mt][nt][q] = 0.f;

    const uint32_t as_base = smem_u32(&As[0][0]);
    const uint32_t bs_base = smem_u32(&Bs[0][0]);

    const int a_row  = lane & 15;
    const int a_col4 = (lane >> 4) * 4;
    const int b_row  = (lane & 7) + ((lane & 16) >> 1);
    const int b_col4 = ((lane >> 3) & 1) * 4;

    #pragma unroll
    for (int kt = 0; kt < 2; kt++) {
        const int f0 = kt * 32;
        #pragma unroll
        for (int l = 0; l < 2; l++) {
            int idx = tid + l * 256;
            int row = idx >> 3, c4 = (idx & 7) * 4;
            *(float4*)&As[row][c4] = *(const float4*)&g_ThT[(m0 + row) * F_ + f0 + c4];
        }
        #pragma unroll
        for (int l = 0; l < 4; l++) {
            int idx = tid + l * 256;
            int row = idx >> 3, c4 = (idx & 7) * 4;
            float4 v;
            if (j0 + row < N_) {
                v = *(const float4*)&xp[(size_t)(j0 + row) * F_ + f0 + c4];
                v.x = to_tf32(v.x); v.y = to_tf32(v.y);
                v.z = to_tf32(v.z); v.w = to_tf32(v.w);
            } else {
                v = make_float4(0.f, 0.f, 0.f, 0.f);
            }
            *(float4*)&Bs[row][c4] = v;
        }
        __syncthreads();

        #pragma unroll
        for (int ks = 0; ks < 4; ks++) {
            const int k0 = ks * 8;
            uint32_t a[2][4];
            #pragma unroll
            for (int mt = 0; mt < 2; mt++) {
                uint32_t addr = as_base +
                    (uint32_t)(((wm + mt * 16 + a_row) * 36 + k0 + a_col4) * 4);
                asm volatile(
                    "ldmatrix.sync.aligned.m8n8.x4.shared.b16 {%0,%1,%2,%3}, [%4];"
                    : "=r"(a[mt][0]), "=r"(a[mt][1]), "=r"(a[mt][2]), "=r"(a[mt][3])
                    : "r"(addr));
            }
            uint32_t bb[4][2];
            #pragma unroll
            for (int nb = 0; nb < 2; nb++) {
                uint32_t addr = bs_base +
                    (uint32_t)(((wn + nb * 16 + b_row) * 36 + k0 + b_col4) * 4);
                uint32_t r0, r1, r2, r3;
                asm volatile(
                    "ldmatrix.sync.aligned.m8n8.x4.shared.b16 {%0,%1,%2,%3}, [%4];"
                    : "=r"(r0), "=r"(r1), "=r"(r2), "=r"(r3)
                    : "r"(addr));
                bb[nb * 2][0] = r0;     bb[nb * 2][1] = r1;
                bb[nb * 2 + 1][0] = r2; bb[nb * 2 + 1][1] = r3;
            }
            #pragma unroll
            for (int mt = 0; mt < 2; mt++)
                #pragma unroll
                for (int nt = 0; nt < 4; nt++)
                    asm volatile(
                        "mma.sync.aligned.m16n8k8.row.col.f32.tf32.tf32.f32 "
                        "{%0,%1,%2,%3}, {%4,%5,%6,%7}, {%8,%9}, {%0,%1,%2,%3};"
                        : "+f"(c[mt][nt][0]), "+f"(c[mt][nt][1]),
                          "+f"(c[mt][nt][2]), "+f"(c[mt][nt][3])
                        : "r"(a[mt][0]), "r"(a[mt][1]), "r"(a[mt][2]), "r"(a[mt][3]),
                          "r"(bb[nt][0]), "r"(bb[nt][1]));
        }
        __syncthreads();
    }

    // Epilogue: write fp16, kj-contiguous
    const int gid = lane >> 2;
    const int tig = lane & 3;
    #pragma unroll
    for (int mt = 0; mt < 2; mt++) {
        #pragma unroll
        for (int half = 0; half < 2; half++) {
            const int ko = m0 + wm + mt * 16 + half * 8 + gid;
            const int k  = ko >> 6;
            const int o  = ko & 63;
            __half* __restrict__ dst =
                g_yT + ((size_t)b * TO_ + t * OUT_ + o) * KJP_ + (size_t)k * N_;
            #pragma unroll
            for (int nt = 0; nt < 4; nt++) {
                const int j = j0 + wn + nt * 8 + tig * 2;
                if (j < N_) {
                    __half2 v;
                    v.x = __float2half_rn(c[mt][nt][half * 2 + 0]);
                    v.y = __float2half_rn(c[mt][nt][half * 2 + 1]);
                    *(__half2*)&dst[j] = v;
                }
            }
        }
    }
}

// ---------------------------------------------------------------------------
// Kernel 2: AT[b][i][kj] = fp16( cheb[kj,i] * SAtt[b, kj%1000, i] )
// cheb cached in registers; b loop inside block.
// ---------------------------------------------------------------------------
__global__ __launch_bounds__(256) void k_buildA(
    const float* __restrict__ SAtt,
    const float* __restrict__ cheb)
{
    __shared__ float buf[256][33];
    const int i0   = blockIdx.y * 32;
    const int kjc  = blockIdx.x * 256;
    const int lane = threadIdx.x & 31;
    const int w    = threadIdx.x >> 5;
    const int i    = i0 + lane;

    float ch[32];
    int   jj[32];
    bool  ok[32];
    #pragma unroll 8
    for (int r = 0; r < 32; r++) {
        const int kj = kjc + w * 32 + r;
        ok[r] = (kj < KJ_) && (i < N_);
        const int k = (kj >= 2000) ? 2 : (kj >= 1000 ? 1 : 0);
        jj[r] = (kj < KJ_) ? (kj - k * 1000) : 0;
        ch[r] = ok[r] ? __ldg(cheb + (size_t)kj * N_ + i) : 0.f;
    }

    for (int b = 0; b < B_; b++) {
        const float* __restrict__ sb = SAtt + (size_t)b * N_ * N_;
        #pragma unroll 8
        for (int r = 0; r < 32; r++) {
            float v = 0.f;
            if (ok[r]) v = ch[r] * __ldg(sb + (size_t)jj[r] * N_ + i);
            buf[w * 32 + r][lane] = v;
        }
        __syncthreads();

        #pragma unroll
        for (int rr = 0; rr < 4; rr++) {
            const int iw = i0 + w * 4 + rr;
            if (iw < N_) {
                __half* __restrict__ outp = g_AT + ((size_t)b * MP_ + iw) * KJP_;
                #pragma unroll
                for (int c = 0; c < 8; c++) {
                    const int kj = kjc + c * 32 + lane;
                    if (kj < KJ_)
                        outp[kj] = __float2half_rn(buf[c * 32 + lane][w * 4 + rr]);
                }
            }
        }
        __syncthreads();
    }
}

// ---------------------------------------------------------------------------
// Kernel 3: spatial GEMM, fp16 m16n8k16, CTA tile 128x256, warp tile 64x64,
// BK=32, 4-stage cp.async ring (wait_group 2), ONE sync per tile.
//   D[b][i][to] = relu( sum_kj AT[b][i][kj] * yT[b][to][kj] )
// ---------------------------------------------------------------------------
#define SBK    32
#define NTILE  (KJP_ / SBK)          // 94
#define BNX    256
#define ROWH   40                    // halfs per smem row (80B, padded)
#define A_STGH (128 * ROWH)          // halfs per A stage
#define B_STGH (BNX * ROWH)          // halfs per B stage
#define STG4   4

__global__ __launch_bounds__(256) void k_spatial_fp16p(float* __restrict__ out)
{
    extern __shared__ __half sm[];
    __half* Asm = sm;                        // [4][128][40]
    __half* Bsm = sm + STG4 * A_STGH;        // [4][256][40]

    const int b  = blockIdx.z;
    const int i0 = blockIdx.y * 128;
    const int n0 = blockIdx.x * BNX;

    const int tid  = threadIdx.x;
    const int lane = tid & 31;
    const int w    = tid >> 5;
    const int im   = (w & 1) * 64;
    const int in_  = (w >> 1) * 64;

    const __half* __restrict__ pA = g_AT + ((size_t)b * MP_ + i0) * KJP_;
    const __half* __restrict__ pB = g_yT + ((size_t)b * TO_ + n0) * KJP_;

    float c[4][8][4];
    #pragma unroll
    for (int mt = 0; mt < 4; mt++)
        #pragma unroll
        for (int nt = 0; nt < 8; nt++)
            #pragma unroll
            for (int q = 0; q < 4; q++) c[mt][nt][q] = 0.f;

    const uint32_t as_base = smem_u32(Asm);
    const uint32_t bs_base = smem_u32(Bsm);

    const int ld_row = tid >> 2;          // 0..63
    const int ld_h0  = (tid & 3) * 8;     // half offset 0,8,16,24

    const int a_row = lane & 15;
    const int a_k8  = lane >> 4;
    const int b_row = (lane & 7) + ((lane & 16) >> 1);
    const int b_k8  = (lane >> 3) & 1;

    #define LOAD_TILE(p, s) do {                                                \
        const uint32_t ao = as_base + (uint32_t)((s) * A_STGH * 2);             \
        const uint32_t bo = bs_base + (uint32_t)((s) * B_STGH * 2);             \
        _Pragma("unroll")                                                       \
        for (int l = 0; l < 2; l++) {                                           \
            const int row = ld_row + l * 64;                                    \
            cpasync16(ao + (uint32_t)((row * ROWH + ld_h0) * 2),                \
                      pA + (size_t)row * KJP_ + (p) + ld_h0);                   \
        }                                                                       \
        _Pragma("unroll")                                                       \
        for (int l = 0; l < 4; l++) {                                           \
            const int row = ld_row + l * 64;                                    \
            cpasync16(bo + (uint32_t)((row * ROWH + ld_h0) * 2),                \
                      pB + (size_t)row * KJP_ + (p) + ld_h0);                   \
        }                                                                       \
        asm volatile("cp.async.commit_group;");                                 \
    } while (0)

    // prologue: tiles 0,1,2
    LOAD_TILE(0, 0);
    LOAD_TILE(SBK, 1);
    LOAD_TILE(2 * SBK, 2);

    for (int pc = 0; pc < NTILE; pc++) {
        const int cur = pc & 3;

        // Ensure tile pc has landed. Outstanding groups at this point:
        // tiles pc..min(pc+2, NTILE-1).
        if (pc < NTILE - 2)       asm volatile("cp.async.wait_group 2;");
        else if (pc == NTILE - 2) asm volatile("cp.async.wait_group 1;");
        else                      asm volatile("cp.async.wait_group 0;");
        __syncthreads();

        // prefetch tile pc+3 into stage (pc+3)&3 = (pc-1)&3 (readers passed the
        // barrier above -> safe to overwrite)
        if (pc + 3 < NTILE) LOAD_TILE((pc + 3) * SBK, (pc + 3) & 3);

        const uint32_t sA = as_base + (uint32_t)(cur * A_STGH * 2);
        const uint32_t sB = bs_base + (uint32_t)(cur * B_STGH * 2);

        #pragma unroll
        for (int ks = 0; ks < 2; ks++) {
            const int kb = ks * 16;

            uint32_t a[4][4];
            #pragma unroll
            for (int mt = 0; mt < 4; mt++) {
                const uint32_t off =
                    (uint32_t)(((im + mt * 16 + a_row) * ROWH + kb + a_k8 * 8) * 2);
                asm volatile(
                    "ldmatrix.sync.aligned.m8n8.x4.shared.b16 {%0,%1,%2,%3}, [%4];"
                    : "=r"(a[mt][0]), "=r"(a[mt][1]), "=r"(a[mt][2]), "=r"(a[mt][3])
                    : "r"(sA + off));
            }
            uint32_t bb[8][2];
            #pragma unroll
            for (int nb = 0; nb < 4; nb++) {
                const uint32_t off =
                    (uint32_t)(((in_ + nb * 16 + b_row) * ROWH + kb + b_k8 * 8) * 2);
                uint32_t r0, r1, r2, r3;
                asm volatile(
                    "ldmatrix.sync.aligned.m8n8.x4.shared.b16 {%0,%1,%2,%3}, [%4];"
                    : "=r"(r0), "=r"(r1), "=r"(r2), "=r"(r3)
                    : "r"(sB + off));
                bb[nb * 2][0] = r0;     bb[nb * 2][1] = r1;
                bb[nb * 2 + 1][0] = r2; bb[nb * 2 + 1][1] = r3;
            }
            #pragma unroll
            for (int mt = 0; mt < 4; mt++)
                #pragma unroll
                for (int nt = 0; nt < 8; nt++)
                    asm volatile(
                        "mma.sync.aligned.m16n8k16.row.col.f32.f16.f16.f32 "
                        "{%0,%1,%2,%3}, {%4,%5,%6,%7}, {%8,%9}, {%0,%1,%2,%3};"
                        : "+f"(c[mt][nt][0]), "+f"(c[mt][nt][1]),
                          "+f"(c[mt][nt][2]), "+f"(c[mt][nt][3])
                        : "r"(a[mt][0]), "r"(a[mt][1]), "r"(a[mt][2]), "r"(a[mt][3]),
                          "r"(bb[nt][0]), "r"(bb[nt][1]));
        }
        // no trailing sync: next iteration's top barrier protects stage reuse
    }

    // Epilogue with fused relu; warp n-extent 64-aligned -> t const per warp
    const int gid = lane >> 2;
    const int tig = lane & 3;
    const int t   = (n0 + in_) >> 6;
    #pragma unroll
    for (int mt = 0; mt < 4; mt++) {
        #pragma unroll
        for (int half = 0; half < 2; half++) {
            const int i = i0 + im + mt * 16 + half * 8 + gid;
            if (i < N_) {
                float* __restrict__ dst =
                    out + (size_t)b * (T_ * N_ * OUT_) + (size_t)t * (N_ * OUT_) +
                    (size_t)i * OUT_;
                #pragma unroll
                for (int nt = 0; nt < 8; nt++) {
                    const int o = nt * 8 + tig * 2;
                    float2 v;
                    v.x = fmaxf(c[mt][nt][half * 2 + 0], 0.f);
                    v.y = fmaxf(c[mt][nt][half * 2 + 1], 0.f);
                    *(float2*)&dst[o] = v;
                }
            }
        }
    }
}

// ---------------------------------------------------------------------------
// Launch
// ---------------------------------------------------------------------------
extern "C" void kernel_launch(void* const* d_in, const int* in_sizes, int n_in,
                              void* d_out, int out_size)
{
    const float* x     = (const float*)d_in[0];
    const float* SAtt  = (const float*)d_in[1];
    const float* cheb  = (const float*)d_in[2];
    const float* Theta = (const float*)d_in[3];
    float* out = (float*)d_out;

    const int smem_sp = STG4 * (A_STGH + B_STGH) * 2;   // 122880 B
    cudaFuncSetAttribute(k_spatial_fp16p,
                         cudaFuncAttributeMaxDynamicSharedMemorySize, smem_sp);

    k_thetaT<<<1, 256>>>(Theta);
    k_featT_tc<<<dim3(8, 3, B_ * T_), 256>>>(x);
    k_buildA<<<dim3(12, 32), 256>>>(SAtt, cheb);
    k_spatial_fp16p<<<dim3(TO_ / BNX, MP_ / 128, B_), 256, smem_sp>>>(out);
}

// round 11
// speedup vs baseline: 2.0433x; 1.0201x over previous
#include <cuda_runtime.h>
#include <cuda_fp16.h>
#include <cstdint>

// Shapes (fixed by the problem)
#define B_   16
#define T_   12
#define N_   1000
#define F_   64
#define KC_  3
#define OUT_ 64

#define KJ_   3000            // contraction dim kj = k*1000 + j
#define KJP_  3008            // padded (mult of 32)
#define MP_   1024            // i padded
#define TO_   768             // t*64 + o

// Scratch (zero-initialized at module load; pad regions never written -> stay 0)
__device__ __align__(256) float  g_ThT[KC_ * OUT_ * F_];          // tf32
__device__ __align__(256) __half g_yT[(size_t)B_ * TO_ * KJP_];   // y  fp16
__device__ __align__(256) __half g_AT[(size_t)B_ * MP_ * KJP_];   // A  fp16

__device__ __forceinline__ float to_tf32(float v) {
    uint32_t u;
    asm("cvt.rna.tf32.f32 %0, %1;" : "=r"(u) : "f"(v));
    return __uint_as_float(u);
}

__device__ __forceinline__ void cpasync16(uint32_t dst, const void* src) {
    asm volatile("cp.async.cg.shared.global [%0], [%1], 16;" :: "r"(dst), "l"(src));
}

__device__ __forceinline__ uint32_t smem_u32(const void* p) {
    uint32_t a;
    asm("{ .reg .u64 t; cvta.to.shared.u64 t, %1; cvt.u32.u64 %0, t; }"
        : "=r"(a) : "l"(p));
    return a;
}

// ---------------------------------------------------------------------------
// Kernel 0: ThT[(k*64+o)][f] = tf32(Theta[k,f,o])
// ---------------------------------------------------------------------------
__global__ __launch_bounds__(256) void k_thetaT(const float* __restrict__ Theta)
{
    for (int idx = threadIdx.x; idx < KC_ * OUT_ * F_; idx += 256) {
        const int f  = idx & 63;
        const int ko = idx >> 6;
        const int k  = ko >> 6;
        const int o  = ko & 63;
        g_ThT[idx] = to_tf32(Theta[(k * F_ + f) * OUT_ + o]);
    }
}

// ---------------------------------------------------------------------------
// Kernel 1: feature transform (mma.sync tf32), fp16 transposed output
//   y[b][t*64+o][k*1000+j] = sum_f ThT[(k*64+o)][f] * x[b,t,j,f]
// ---------------------------------------------------------------------------
__global__ __launch_bounds__(256) void k_featT_tc(const float* __restrict__ x)
{
    __shared__ float As[64][36];
    __shared__ float Bs[128][36];

    const int j0 = blockIdx.x * 128;
    const int m0 = blockIdx.y * 64;
    const int bt = blockIdx.z;
    const int b  = bt / T_;
    const int t  = bt % T_;

    const int tid  = threadIdx.x;
    const int lane = tid & 31;
    const int w    = tid >> 5;
    const int wm   = (w & 1) * 32;
    const int wn   = (w >> 1) * 32;

    const float* __restrict__ xp = x + (size_t)bt * N_ * F_;

    float c[2][4][4];
    #pragma unroll
    for (int mt = 0; mt < 2; mt++)
        #pragma unroll
        for (int nt = 0; nt < 4; nt++)
            #pragma unroll
            for (int q = 0; q < 4; q++) c[mt][nt][q] = 0.f;

    const uint32_t as_base = smem_u32(&As[0][0]);
    const uint32_t bs_base = smem_u32(&Bs[0][0]);

    const int a_row  = lane & 15;
    const int a_col4 = (lane >> 4) * 4;
    const int b_row  = (lane & 7) + ((lane & 16) >> 1);
    const int b_col4 = ((lane >> 3) & 1) * 4;

    #pragma unroll
    for (int kt = 0; kt < 2; kt++) {
        const int f0 = kt * 32;
        #pragma unroll
        for (int l = 0; l < 2; l++) {
            int idx = tid + l * 256;
            int row = idx >> 3, c4 = (idx & 7) * 4;
            *(float4*)&As[row][c4] = *(const float4*)&g_ThT[(m0 + row) * F_ + f0 + c4];
        }
        #pragma unroll
        for (int l = 0; l < 4; l++) {
            int idx = tid + l * 256;
            int row = idx >> 3, c4 = (idx & 7) * 4;
            float4 v;
            if (j0 + row < N_) {
                v = *(const float4*)&xp[(size_t)(j0 + row) * F_ + f0 + c4];
                v.x = to_tf32(v.x); v.y = to_tf32(v.y);
                v.z = to_tf32(v.z); v.w = to_tf32(v.w);
            } else {
                v = make_float4(0.f, 0.f, 0.f, 0.f);
            }
            *(float4*)&Bs[row][c4] = v;
        }
        __syncthreads();

        #pragma unroll
        for (int ks = 0; ks < 4; ks++) {
            const int k0 = ks * 8;
            uint32_t a[2][4];
            #pragma unroll
            for (int mt = 0; mt < 2; mt++) {
                uint32_t addr = as_base +
                    (uint32_t)(((wm + mt * 16 + a_row) * 36 + k0 + a_col4) * 4);
                asm volatile(
                    "ldmatrix.sync.aligned.m8n8.x4.shared.b16 {%0,%1,%2,%3}, [%4];"
                    : "=r"(a[mt][0]), "=r"(a[mt][1]), "=r"(a[mt][2]), "=r"(a[mt][3])
                    : "r"(addr));
            }
            uint32_t bb[4][2];
            #pragma unroll
            for (int nb = 0; nb < 2; nb++) {
                uint32_t addr = bs_base +
                    (uint32_t)(((wn + nb * 16 + b_row) * 36 + k0 + b_col4) * 4);
                uint32_t r0, r1, r2, r3;
                asm volatile(
                    "ldmatrix.sync.aligned.m8n8.x4.shared.b16 {%0,%1,%2,%3}, [%4];"
                    : "=r"(r0), "=r"(r1), "=r"(r2), "=r"(r3)
                    : "r"(addr));
                bb[nb * 2][0] = r0;     bb[nb * 2][1] = r1;
                bb[nb * 2 + 1][0] = r2; bb[nb * 2 + 1][1] = r3;
            }
            #pragma unroll
            for (int mt = 0; mt < 2; mt++)
                #pragma unroll
                for (int nt = 0; nt < 4; nt++)
                    asm volatile(
                        "mma.sync.aligned.m16n8k8.row.col.f32.tf32.tf32.f32 "
                        "{%0,%1,%2,%3}, {%4,%5,%6,%7}, {%8,%9}, {%0,%1,%2,%3};"
                        : "+f"(c[mt][nt][0]), "+f"(c[mt][nt][1]),
                          "+f"(c[mt][nt][2]), "+f"(c[mt][nt][3])
                        : "r"(a[mt][0]), "r"(a[mt][1]), "r"(a[mt][2]), "r"(a[mt][3]),
                          "r"(bb[nt][0]), "r"(bb[nt][1]));
        }
        __syncthreads();
    }

    // Epilogue: write fp16, kj-contiguous
    const int gid = lane >> 2;
    const int tig = lane & 3;
    #pragma unroll
    for (int mt = 0; mt < 2; mt++) {
        #pragma unroll
        for (int half = 0; half < 2; half++) {
            const int ko = m0 + wm + mt * 16 + half * 8 + gid;
            const int k  = ko >> 6;
            const int o  = ko & 63;
            __half* __restrict__ dst =
                g_yT + ((size_t)b * TO_ + t * OUT_ + o) * KJP_ + (size_t)k * N_;
            #pragma unroll
            for (int nt = 0; nt < 4; nt++) {
                const int j = j0 + wn + nt * 8 + tig * 2;
                if (j < N_) {
                    __half2 v;
                    v.x = __float2half_rn(c[mt][nt][half * 2 + 0]);
                    v.y = __float2half_rn(c[mt][nt][half * 2 + 1]);
                    *(__half2*)&dst[j] = v;
                }
            }
        }
    }
}

// ---------------------------------------------------------------------------
// Kernel 2: AT[b][i][kj] = fp16( cheb[kj,i] * SAtt[b, kj%1000, i] )
// ---------------------------------------------------------------------------
__global__ __launch_bounds__(256) void k_buildA(
    const float* __restrict__ SAtt,
    const float* __restrict__ cheb)
{
    __shared__ float buf[256][33];
    const int i0   = blockIdx.y * 32;
    const int kjc  = blockIdx.x * 256;
    const int lane = threadIdx.x & 31;
    const int w    = threadIdx.x >> 5;
    const int i    = i0 + lane;

    float ch[32];
    int   jj[32];
    bool  ok[32];
    #pragma unroll 8
    for (int r = 0; r < 32; r++) {
        const int kj = kjc + w * 32 + r;
        ok[r] = (kj < KJ_) && (i < N_);
        const int k = (kj >= 2000) ? 2 : (kj >= 1000 ? 1 : 0);
        jj[r] = (kj < KJ_) ? (kj - k * 1000) : 0;
        ch[r] = ok[r] ? __ldg(cheb + (size_t)kj * N_ + i) : 0.f;
    }

    for (int b = 0; b < B_; b++) {
        const float* __restrict__ sb = SAtt + (size_t)b * N_ * N_;
        #pragma unroll 8
        for (int r = 0; r < 32; r++) {
            float v = 0.f;
            if (ok[r]) v = ch[r] * __ldg(sb + (size_t)jj[r] * N_ + i);
            buf[w * 32 + r][lane] = v;
        }
        __syncthreads();

        #pragma unroll
        for (int rr = 0; rr < 4; rr++) {
            const int iw = i0 + w * 4 + rr;
            if (iw < N_) {
                __half* __restrict__ outp = g_AT + ((size_t)b * MP_ + iw) * KJP_;
                #pragma unroll
                for (int c = 0; c < 8; c++) {
                    const int kj = kjc + c * 32 + lane;
                    if (kj < KJ_)
                        outp[kj] = __float2half_rn(buf[c * 32 + lane][w * 4 + rr]);
                }
            }
        }
        __syncthreads();
    }
}

// ---------------------------------------------------------------------------
// Kernel 3: spatial GEMM, fp16 m16n8k16, CTA 128x256, 512 threads / 16 warps,
// warp tile 64x32 (2m x 8n), BK=32, 4-stage cp.async ring, ONE sync per tile.
//   D[b][i][to] = relu( sum_kj AT[b][i][kj] * yT[b][to][kj] )
// ---------------------------------------------------------------------------
#define SBK    32
#define NTILE  (KJP_ / SBK)          // 94
#define BNX    256
#define ROWH   40                    // halfs per smem row (80B, padded)
#define A_STGH (128 * ROWH)
#define B_STGH (BNX * ROWH)
#define STG4   4

__global__ __launch_bounds__(512) void k_spatial_fp16w(float* __restrict__ out)
{
    extern __shared__ __half sm[];
    __half* Asm = sm;                        // [4][128][40]
    __half* Bsm = sm + STG4 * A_STGH;        // [4][256][40]

    const int b  = blockIdx.z;
    const int i0 = blockIdx.y * 128;
    const int n0 = blockIdx.x * BNX;

    const int tid  = threadIdx.x;
    const int lane = tid & 31;
    const int w    = tid >> 5;            // 0..15
    const int im   = (w & 1) * 64;        // warp m-origin (2 strips)
    const int in_  = (w >> 1) * 32;       // warp n-origin (8 strips)

    const __half* __restrict__ pA = g_AT + ((size_t)b * MP_ + i0) * KJP_;
    const __half* __restrict__ pB = g_yT + ((size_t)b * TO_ + n0) * KJP_;

    float c[4][4][4];
    #pragma unroll
    for (int mt = 0; mt < 4; mt++)
        #pragma unroll
        for (int nt = 0; nt < 4; nt++)
            #pragma unroll
            for (int q = 0; q < 4; q++) c[mt][nt][q] = 0.f;

    const uint32_t as_base = smem_u32(Asm);
    const uint32_t bs_base = smem_u32(Bsm);

    // loader: A = 512 x 16B chunks (1/thread), B = 1024 (2/thread)
    const int ld_row = tid >> 2;          // 0..127
    const int ld_h0  = (tid & 3) * 8;     // half offset 0,8,16,24

    const int a_row = lane & 15;
    const int a_k8  = lane >> 4;
    const int b_row = (lane & 7) + ((lane & 16) >> 1);
    const int b_k8  = (lane >> 3) & 1;

    #define LOAD_TILE(p, s) do {                                                \
        const uint32_t ao = as_base + (uint32_t)((s) * A_STGH * 2);             \
        const uint32_t bo = bs_base + (uint32_t)((s) * B_STGH * 2);             \
        cpasync16(ao + (uint32_t)((ld_row * ROWH + ld_h0) * 2),                 \
                  pA + (size_t)ld_row * KJP_ + (p) + ld_h0);                    \
        cpasync16(bo + (uint32_t)((ld_row * ROWH + ld_h0) * 2),                 \
                  pB + (size_t)ld_row * KJP_ + (p) + ld_h0);                    \
        cpasync16(bo + (uint32_t)(((ld_row + 128) * ROWH + ld_h0) * 2),         \
                  pB + (size_t)(ld_row + 128) * KJP_ + (p) + ld_h0);            \
        asm volatile("cp.async.commit_group;");                                 \
    } while (0)

    // prologue: tiles 0,1,2
    LOAD_TILE(0, 0);
    LOAD_TILE(SBK, 1);
    LOAD_TILE(2 * SBK, 2);

    for (int pc = 0; pc < NTILE; pc++) {
        const int cur = pc & 3;

        if (pc < NTILE - 2)       asm volatile("cp.async.wait_group 2;");
        else if (pc == NTILE - 2) asm volatile("cp.async.wait_group 1;");
        else                      asm volatile("cp.async.wait_group 0;");
        __syncthreads();

        if (pc + 3 < NTILE) LOAD_TILE((pc + 3) * SBK, (pc + 3) & 3);

        const uint32_t sA = as_base + (uint32_t)(cur * A_STGH * 2);
        const uint32_t sB = bs_base + (uint32_t)(cur * B_STGH * 2);

        #pragma unroll
        for (int ks = 0; ks < 2; ks++) {
            const int kb = ks * 16;

            uint32_t a[4][4];
            #pragma unroll
            for (int mt = 0; mt < 4; mt++) {
                const uint32_t off =
                    (uint32_t)(((im + mt * 16 + a_row) * ROWH + kb + a_k8 * 8) * 2);
                asm volatile(
                    "ldmatrix.sync.aligned.m8n8.x4.shared.b16 {%0,%1,%2,%3}, [%4];"
                    : "=r"(a[mt][0]), "=r"(a[mt][1]), "=r"(a[mt][2]), "=r"(a[mt][3])
                    : "r"(sA + off));
            }
            uint32_t bb[4][2];
            #pragma unroll
            for (int nb = 0; nb < 2; nb++) {
                const uint32_t off =
                    (uint32_t)(((in_ + nb * 16 + b_row) * ROWH + kb + b_k8 * 8) * 2);
                uint32_t r0, r1, r2, r3;
                asm volatile(
                    "ldmatrix.sync.aligned.m8n8.x4.shared.b16 {%0,%1,%2,%3}, [%4];"
                    : "=r"(r0), "=r"(r1), "=r"(r2), "=r"(r3)
                    : "r"(sB + off));
                bb[nb * 2][0] = r0;     bb[nb * 2][1] = r1;
                bb[nb * 2 + 1][0] = r2; bb[nb * 2 + 1][1] = r3;
            }
            #pragma unroll
            for (int mt = 0; mt < 4; mt++)
                #pragma unroll
                for (int nt = 0; nt < 4; nt++)
                    asm volatile(
                        "mma.sync.aligned.m16n8k16.row.col.f32.f16.f16.f32 "
                        "{%0,%1,%2,%3}, {%4,%5,%6,%7}, {%8,%9}, {%0,%1,%2,%3};"
                        : "+f"(c[mt][nt][0]), "+f"(c[mt][nt][1]),
                          "+f"(c[mt][nt][2]), "+f"(c[mt][nt][3])
                        : "r"(a[mt][0]), "r"(a[mt][1]), "r"(a[mt][2]), "r"(a[mt][3]),
                          "r"(bb[nt][0]), "r"(bb[nt][1]));
        }
        // no trailing sync; next iteration's barrier protects stage reuse
    }

    // Epilogue with fused relu. Warp n-extent 32, 32-aligned -> t const.
    const int gid = lane >> 2;
    const int tig = lane & 3;
    const int t   = (n0 + in_) >> 6;
    const int o0  = (n0 + in_) & 63;
    #pragma unroll
    for (int mt = 0; mt < 4; mt++) {
        #pragma unroll
        for (int half = 0; half < 2; half++) {
            const int i = i0 + im + mt * 16 + half * 8 + gid;
            if (i < N_) {
                float* __restrict__ dst =
                    out + (size_t)b * (T_ * N_ * OUT_) + (size_t)t * (N_ * OUT_) +
                    (size_t)i * OUT_ + o0;
                #pragma unroll
                for (int nt = 0; nt < 4; nt++) {
                    const int o = nt * 8 + tig * 2;
                    float2 v;
                    v.x = fmaxf(c[mt][nt][half * 2 + 0], 0.f);
                    v.y = fmaxf(c[mt][nt][half * 2 + 1], 0.f);
                    *(float2*)&dst[o] = v;
                }
            }
        }
    }
}

// ---------------------------------------------------------------------------
// Launch
// ---------------------------------------------------------------------------
extern "C" void kernel_launch(void* const* d_in, const int* in_sizes, int n_in,
                              void* d_out, int out_size)
{
    const float* x     = (const float*)d_in[0];
    const float* SAtt  = (const float*)d_in[1];
    const float* cheb  = (const float*)d_in[2];
    const float* Theta = (const float*)d_in[3];
    float* out = (float*)d_out;

    const int smem_sp = STG4 * (A_STGH + B_STGH) * 2;   // 122880 B
    cudaFuncSetAttribute(k_spatial_fp16w,
                         cudaFuncAttributeMaxDynamicSharedMemorySize, smem_sp);

    k_thetaT<<<1, 256>>>(Theta);
    k_featT_tc<<<dim3(8, 3, B_ * T_), 256>>>(x);
    k_buildA<<<dim3(12, 32), 256>>>(SAtt, cheb);
    k_spatial_fp16w<<<dim3(TO_ / BNX, MP_ / 128, B_), 512, smem_sp>>>(out);
}

// round 12
// speedup vs baseline: 2.4719x; 1.2098x over previous
#include <cuda_runtime.h>
#include <cuda_fp16.h>
#include <cstdint>

// Shapes (fixed by the problem)
#define B_   16
#define T_   12
#define N_   1000
#define F_   64
#define KC_  3
#define OUT_ 64

#define KJ_   3000            // contraction dim kj = k*1000 + j
#define KJP_  3008            // padded (mult of 64 here: 3008 = 47*64)
#define MP_   1024            // i padded
#define TO_   768             // t*64 + o

// Scratch (zero-initialized at module load; pad regions never written -> stay 0)
__device__ __align__(256) float  g_ThT[KC_ * OUT_ * F_];          // tf32
__device__ __align__(256) __half g_yT[(size_t)B_ * TO_ * KJP_];   // y  fp16
__device__ __align__(256) __half g_AT[(size_t)B_ * MP_ * KJP_];   // A  fp16

__device__ __forceinline__ float to_tf32(float v) {
    uint32_t u;
    asm("cvt.rna.tf32.f32 %0, %1;" : "=r"(u) : "f"(v));
    return __uint_as_float(u);
}

__device__ __forceinline__ void cpasync16(uint32_t dst, const void* src) {
    asm volatile("cp.async.cg.shared.global [%0], [%1], 16;" :: "r"(dst), "l"(src));
}

__device__ __forceinline__ uint32_t smem_u32(const void* p) {
    uint32_t a;
    asm("{ .reg .u64 t; cvta.to.shared.u64 t, %1; cvt.u32.u64 %0, t; }"
        : "=r"(a) : "l"(p));
    return a;
}

// ---------------------------------------------------------------------------
// Kernel 0: ThT[(k*64+o)][f] = tf32(Theta[k,f,o])
// ---------------------------------------------------------------------------
__global__ __launch_bounds__(256) void k_thetaT(const float* __restrict__ Theta)
{
    for (int idx = threadIdx.x; idx < KC_ * OUT_ * F_; idx += 256) {
        const int f  = idx & 63;
        const int ko = idx >> 6;
        const int k  = ko >> 6;
        const int o  = ko & 63;
        g_ThT[idx] = to_tf32(Theta[(k * F_ + f) * OUT_ + o]);
    }
}

// ---------------------------------------------------------------------------
// Kernel 1: feature transform (mma.sync tf32), fp16 transposed output
//   y[b][t*64+o][k*1000+j] = sum_f ThT[(k*64+o)][f] * x[b,t,j,f]
// ---------------------------------------------------------------------------
__global__ __launch_bounds__(256) void k_featT_tc(const float* __restrict__ x)
{
    __shared__ float As[64][36];
    __shared__ float Bs[128][36];

    const int j0 = blockIdx.x * 128;
    const int m0 = blockIdx.y * 64;
    const int bt = blockIdx.z;
    const int b  = bt / T_;
    const int t  = bt % T_;

    const int tid  = threadIdx.x;
    const int lane = tid & 31;
    const int w    = tid >> 5;
    const int wm   = (w & 1) * 32;
    const int wn   = (w >> 1) * 32;

    const float* __restrict__ xp = x + (size_t)bt * N_ * F_;

    float c[2][4][4];
    #pragma unroll
    for (int mt = 0; mt < 2; mt++)
        #pragma unroll
        for (int nt = 0; nt < 4; nt++)
            #pragma unroll
            for (int q = 0; q < 4; q++) c[mt][nt][q] = 0.f;

    const uint32_t as_base = smem_u32(&As[0][0]);
    const uint32_t bs_base = smem_u32(&Bs[0][0]);

    const int a_row  = lane & 15;
    const int a_col4 = (lane >> 4) * 4;
    const int b_row  = (lane & 7) + ((lane & 16) >> 1);
    const int b_col4 = ((lane >> 3) & 1) * 4;

    #pragma unroll
    for (int kt = 0; kt < 2; kt++) {
        const int f0 = kt * 32;
        #pragma unroll
        for (int l = 0; l < 2; l++) {
            int idx = tid + l * 256;
            int row = idx >> 3, c4 = (idx & 7) * 4;
            *(float4*)&As[row][c4] = *(const float4*)&g_ThT[(m0 + row) * F_ + f0 + c4];
        }
        #pragma unroll
        for (int l = 0; l < 4; l++) {
            int idx = tid + l * 256;
            int row = idx >> 3, c4 = (idx & 7) * 4;
            float4 v;
            if (j0 + row < N_) {
                v = *(const float4*)&xp[(size_t)(j0 + row) * F_ + f0 + c4];
                v.x = to_tf32(v.x); v.y = to_tf32(v.y);
                v.z = to_tf32(v.z); v.w = to_tf32(v.w);
            } else {
                v = make_float4(0.f, 0.f, 0.f, 0.f);
            }
            *(float4*)&Bs[row][c4] = v;
        }
        __syncthreads();

        #pragma unroll
        for (int ks = 0; ks < 4; ks++) {
            const int k0 = ks * 8;
            uint32_t a[2][4];
            #pragma unroll
            for (int mt = 0; mt < 2; mt++) {
                uint32_t addr = as_base +
                    (uint32_t)(((wm + mt * 16 + a_row) * 36 + k0 + a_col4) * 4);
                asm volatile(
                    "ldmatrix.sync.aligned.m8n8.x4.shared.b16 {%0,%1,%2,%3}, [%4];"
                    : "=r"(a[mt][0]), "=r"(a[mt][1]), "=r"(a[mt][2]), "=r"(a[mt][3])
                    : "r"(addr));
            }
            uint32_t bb[4][2];
            #pragma unroll
            for (int nb = 0; nb < 2; nb++) {
                uint32_t addr = bs_base +
                    (uint32_t)(((wn + nb * 16 + b_row) * 36 + k0 + b_col4) * 4);
                uint32_t r0, r1, r2, r3;
                asm volatile(
                    "ldmatrix.sync.aligned.m8n8.x4.shared.b16 {%0,%1,%2,%3}, [%4];"
                    : "=r"(r0), "=r"(r1), "=r"(r2), "=r"(r3)
                    : "r"(addr));
                bb[nb * 2][0] = r0;     bb[nb * 2][1] = r1;
                bb[nb * 2 + 1][0] = r2; bb[nb * 2 + 1][1] = r3;
            }
            #pragma unroll
            for (int mt = 0; mt < 2; mt++)
                #pragma unroll
                for (int nt = 0; nt < 4; nt++)
                    asm volatile(
                        "mma.sync.aligned.m16n8k8.row.col.f32.tf32.tf32.f32 "
                        "{%0,%1,%2,%3}, {%4,%5,%6,%7}, {%8,%9}, {%0,%1,%2,%3};"
                        : "+f"(c[mt][nt][0]), "+f"(c[mt][nt][1]),
                          "+f"(c[mt][nt][2]), "+f"(c[mt][nt][3])
                        : "r"(a[mt][0]), "r"(a[mt][1]), "r"(a[mt][2]), "r"(a[mt][3]),
                          "r"(bb[nt][0]), "r"(bb[nt][1]));
        }
        __syncthreads();
    }

    // Epilogue: write fp16, kj-contiguous
    const int gid = lane >> 2;
    const int tig = lane & 3;
    #pragma unroll
    for (int mt = 0; mt < 2; mt++) {
        #pragma unroll
        for (int half = 0; half < 2; half++) {
            const int ko = m0 + wm + mt * 16 + half * 8 + gid;
            const int k  = ko >> 6;
            const int o  = ko & 63;
            __half* __restrict__ dst =
                g_yT + ((size_t)b * TO_ + t * OUT_ + o) * KJP_ + (size_t)k * N_;
            #pragma unroll
            for (int nt = 0; nt < 4; nt++) {
                const int j = j0 + wn + nt * 8 + tig * 2;
                if (j < N_) {
                    __half2 v;
                    v.x = __float2half_rn(c[mt][nt][half * 2 + 0]);
                    v.y = __float2half_rn(c[mt][nt][half * 2 + 1]);
                    *(__half2*)&dst[j] = v;
                }
            }
        }
    }
}

// ---------------------------------------------------------------------------
// Kernel 2: AT[b][i][kj] = fp16( cheb[kj,i] * SAtt[b, kj%1000, i] )
// Per-b grid (R5/R6 form — measured faster than the b-loop variant).
// ---------------------------------------------------------------------------
__global__ __launch_bounds__(256) void k_buildA(
    const float* __restrict__ SAtt,
    const float* __restrict__ cheb)
{
    __shared__ float buf[256][33];
    const int b    = blockIdx.z;
    const int i0   = blockIdx.y * 32;
    const int kjc  = blockIdx.x * 256;
    const int lane = threadIdx.x & 31;
    const int w    = threadIdx.x >> 5;
    const int i    = i0 + lane;

    const float* __restrict__ sb = SAtt + (size_t)b * N_ * N_;

    #pragma unroll 4
    for (int r = 0; r < 32; r++) {
        int kj = kjc + w * 32 + r;
        float v = 0.f;
        if (kj < KJ_ && i < N_) {
            int k = (kj >= 2000) ? 2 : (kj >= 1000 ? 1 : 0);
            int j = kj - k * 1000;
            v = __ldg(cheb + (size_t)kj * N_ + i) * __ldg(sb + (size_t)j * N_ + i);
        }
        buf[w * 32 + r][lane] = v;
    }
    __syncthreads();

    #pragma unroll
    for (int rr = 0; rr < 4; rr++) {
        int iw = i0 + w * 4 + rr;
        if (iw < N_) {
            __half* __restrict__ outp = g_AT + ((size_t)b * MP_ + iw) * KJP_;
            #pragma unroll
            for (int c = 0; c < 8; c++) {
                int kj = kjc + c * 32 + lane;
                if (kj < KJ_)
                    outp[kj] = __float2half_rn(buf[c * 32 + lane][w * 4 + rr]);
            }
        }
    }
}

// ---------------------------------------------------------------------------
// Kernel 3: spatial GEMM, fp16 m16n8k16, CTA 128x256, 512 thr / 16 warps,
// warp tile 64x32, BK=64, 3-stage cp.async ring, ONE sync per tile (47 tiles).
//   D[b][i][to] = relu( sum_kj AT[b][i][kj] * yT[b][to][kj] )
// ---------------------------------------------------------------------------
#define SBK    64
#define NTILE  (KJP_ / SBK)          // 47
#define BNX    256
#define ROWH   72                    // halfs per smem row (144B, 16B-pad)
#define A_STGH (128 * ROWH)          // 9216 halfs = 18 KB
#define B_STGH (BNX * ROWH)          // 18432 halfs = 36 KB
#define STG3   3

__global__ __launch_bounds__(512) void k_spatial_fp16k(float* __restrict__ out)
{
    extern __shared__ __half sm[];
    __half* Asm = sm;                        // [3][128][72]
    __half* Bsm = sm + STG3 * A_STGH;        // [3][256][72]

    const int b  = blockIdx.z;
    const int i0 = blockIdx.y * 128;
    const int n0 = blockIdx.x * BNX;

    const int tid  = threadIdx.x;
    const int lane = tid & 31;
    const int w    = tid >> 5;            // 0..15
    const int im   = (w & 1) * 64;        // warp m-origin
    const int in_  = (w >> 1) * 32;       // warp n-origin

    const __half* __restrict__ pA = g_AT + ((size_t)b * MP_ + i0) * KJP_;
    const __half* __restrict__ pB = g_yT + ((size_t)b * TO_ + n0) * KJP_;

    float c[4][4][4];
    #pragma unroll
    for (int mt = 0; mt < 4; mt++)
        #pragma unroll
        for (int nt = 0; nt < 4; nt++)
            #pragma unroll
            for (int q = 0; q < 4; q++) c[mt][nt][q] = 0.f;

    const uint32_t as_base = smem_u32(Asm);
    const uint32_t bs_base = smem_u32(Bsm);

    // loader: rows of 64 halfs = 8 x 16B chunks. A: 2/thread, B: 4/thread.
    const int ld_row = tid >> 3;          // 0..63
    const int ld_h0  = (tid & 7) * 8;     // half offset 0..56

    const int a_row = lane & 15;
    const int a_k8  = lane >> 4;
    const int b_row = (lane & 7) + ((lane & 16) >> 1);
    const int b_k8  = (lane >> 3) & 1;

    #define LOAD_TILE(p, s) do {                                                \
        const uint32_t ao = as_base + (uint32_t)((s) * A_STGH * 2);             \
        const uint32_t bo = bs_base + (uint32_t)((s) * B_STGH * 2);             \
        _Pragma("unroll")                                                       \
        for (int l = 0; l < 2; l++) {                                           \
            const int row = ld_row + l * 64;                                    \
            cpasync16(ao + (uint32_t)((row * ROWH + ld_h0) * 2),                \
                      pA + (size_t)row * KJP_ + (p) + ld_h0);                   \
        }                                                                       \
        _Pragma("unroll")                                                       \
        for (int l = 0; l < 4; l++) {                                           \
            const int row = ld_row + l * 64;                                    \
            cpasync16(bo + (uint32_t)((row * ROWH + ld_h0) * 2),                \
                      pB + (size_t)row * KJP_ + (p) + ld_h0);                   \
        }                                                                       \
        asm volatile("cp.async.commit_group;");                                 \
    } while (0)

    // prologue: tiles 0,1
    LOAD_TILE(0, 0);
    LOAD_TILE(SBK, 1);

    for (int pc = 0; pc < NTILE; pc++) {
        const int cur = pc % STG3;

        // outstanding groups here: tiles pc and (pc+1 if it exists)
        if (pc < NTILE - 1) asm volatile("cp.async.wait_group 1;");
        else                asm volatile("cp.async.wait_group 0;");
        __syncthreads();

        // prefetch tile pc+2 into stage (pc+2)%3 = (pc-1)%3 (readers done)
        if (pc + 2 < NTILE) LOAD_TILE((pc + 2) * SBK, (pc + 2) % STG3);

        const uint32_t sA = as_base + (uint32_t)(cur * A_STGH * 2);
        const uint32_t sB = bs_base + (uint32_t)(cur * B_STGH * 2);

        #pragma unroll
        for (int ks = 0; ks < 4; ks++) {
            const int kb = ks * 16;

            uint32_t a[4][4];
            #pragma unroll
            for (int mt = 0; mt < 4; mt++) {
                const uint32_t off =
                    (uint32_t)(((im + mt * 16 + a_row) * ROWH + kb + a_k8 * 8) * 2);
                asm volatile(
                    "ldmatrix.sync.aligned.m8n8.x4.shared.b16 {%0,%1,%2,%3}, [%4];"
                    : "=r"(a[mt][0]), "=r"(a[mt][1]), "=r"(a[mt][2]), "=r"(a[mt][3])
                    : "r"(sA + off));
            }
            uint32_t bb[4][2];
            #pragma unroll
            for (int nb = 0; nb < 2; nb++) {
                const uint32_t off =
                    (uint32_t)(((in_ + nb * 16 + b_row) * ROWH + kb + b_k8 * 8) * 2);
                uint32_t r0, r1, r2, r3;
                asm volatile(
                    "ldmatrix.sync.aligned.m8n8.x4.shared.b16 {%0,%1,%2,%3}, [%4];"
                    : "=r"(r0), "=r"(r1), "=r"(r2), "=r"(r3)
                    : "r"(sB + off));
                bb[nb * 2][0] = r0;     bb[nb * 2][1] = r1;
                bb[nb * 2 + 1][0] = r2; bb[nb * 2 + 1][1] = r3;
            }
            #pragma unroll
            for (int mt = 0; mt < 4; mt++)
                #pragma unroll
                for (int nt = 0; nt < 4; nt++)
                    asm volatile(
                        "mma.sync.aligned.m16n8k16.row.col.f32.f16.f16.f32 "
                        "{%0,%1,%2,%3}, {%4,%5,%6,%7}, {%8,%9}, {%0,%1,%2,%3};"
                        : "+f"(c[mt][nt][0]), "+f"(c[mt][nt][1]),
                          "+f"(c[mt][nt][2]), "+f"(c[mt][nt][3])
                        : "r"(a[mt][0]), "r"(a[mt][1]), "r"(a[mt][2]), "r"(a[mt][3]),
                          "r"(bb[nt][0]), "r"(bb[nt][1]));
        }
        // no trailing sync; next iteration's barrier protects stage reuse
    }

    // Epilogue with fused relu. Warp n-extent 32, 32-aligned -> t const.
    const int gid = lane >> 2;
    const int tig = lane & 3;
    const int t   = (n0 + in_) >> 6;
    const int o0  = (n0 + in_) & 63;
    #pragma unroll
    for (int mt = 0; mt < 4; mt++) {
        #pragma unroll
        for (int half = 0; half < 2; half++) {
            const int i = i0 + im + mt * 16 + half * 8 + gid;
            if (i < N_) {
                float* __restrict__ dst =
                    out + (size_t)b * (T_ * N_ * OUT_) + (size_t)t * (N_ * OUT_) +
                    (size_t)i * OUT_ + o0;
                #pragma unroll
                for (int nt = 0; nt < 4; nt++) {
                    const int o = nt * 8 + tig * 2;
                    float2 v;
                    v.x = fmaxf(c[mt][nt][half * 2 + 0], 0.f);
                    v.y = fmaxf(c[mt][nt][half * 2 + 1], 0.f);
                    *(float2*)&dst[o] = v;
                }
            }
        }
    }
}

// ---------------------------------------------------------------------------
// Launch
// ---------------------------------------------------------------------------
extern "C" void kernel_launch(void* const* d_in, const int* in_sizes, int n_in,
                              void* d_out, int out_size)
{
    const float* x     = (const float*)d_in[0];
    const float* SAtt  = (const float*)d_in[1];
    const float* cheb  = (const float*)d_in[2];
    const float* Theta = (const float*)d_in[3];
    float* out = (float*)d_out;

    const int smem_sp = STG3 * (A_STGH + B_STGH) * 2;   // 165888 B
    cudaFuncSetAttribute(k_spatial_fp16k,
                         cudaFuncAttributeMaxDynamicSharedMemorySize, smem_sp);

    k_thetaT<<<1, 256>>>(Theta);
    k_featT_tc<<<dim3(8, 3, B_ * T_), 256>>>(x);
    k_buildA<<<dim3(12, 32, B_), 256>>>(SAtt, cheb);
    k_spatial_fp16k<<<dim3(TO_ / BNX, MP_ / 128, B_), 512, smem_sp>>>(out);
}